// round 10
// baseline (speedup 1.0000x reference)
#include <cuda_runtime.h>
#include <cuda_fp16.h>
#include <cstdint>
#include <math.h>

#define NBATCH 2
#define SEQ    4096
#define EMB    1024
#define FFDIM  4096
#define MROWS  (NBATCH*SEQ)   // 8192

#define SVAL 0.00390625f      // s = 2^-8
#define SINV 256.0f           // 1/s

typedef __half h16;

// ---------------- scratch (device globals; allocation-free) ----------------
__device__ h16 qin_h[MROWS*EMB], qin_2[MROWS*EMB];      // A-style
__device__ h16 kin_h[MROWS*EMB], kin_2[MROWS*EMB];      // A-style
__device__ h16 vin_h[MROWS*EMB], vin_2[MROWS*EMB];      // A-style
__device__ h16 wq_h[EMB*EMB],   wq_2[EMB*EMB];          // B-style
__device__ h16 wk_h[EMB*EMB],   wk_2[EMB*EMB];          // B-style
__device__ h16 wv_h[EMB*EMB],   wv_2[EMB*EMB];          // B-style
__device__ h16 w1_h[FFDIM*EMB], w1_2[FFDIM*EMB];        // B-style
__device__ h16 w2_h[EMB*FFDIM], w2_2[EMB*FFDIM];        // B-style
__device__ h16 q_h[MROWS*EMB],  q_2[MROWS*EMB];         // A-style
__device__ h16 k_h[MROWS*EMB],  k_2[MROWS*EMB];         // B-style
__device__ h16 vt_h[NBATCH*EMB*SEQ], vt_2[NBATCH*EMB*SEQ];  // B-style
__device__ h16 at_h[(size_t)NBATCH*SEQ*SEQ], at_2[(size_t)NBATCH*SEQ*SEQ]; // A-style
__device__ h16 x_h[MROWS*EMB],  x_2[MROWS*EMB];         // A-style
__device__ h16 h_h[MROWS*FFDIM], h_2[MROWS*FFDIM];      // A-style
__device__ float g_attnf[(size_t)NBATCH*SEQ*SEQ];
__device__ float g_x[MROWS*EMB];
__device__ float g_y[MROWS*EMB];

// ---------------- helpers ----------------
__device__ __forceinline__ uint32_t smem_u32(const void* p) {
    uint32_t a;
    asm("{ .reg .u64 t; cvta.to.shared.u64 t, %1; cvt.u32.u64 %0, t; }" : "=r"(a) : "l"(p));
    return a;
}
__device__ __forceinline__ void ldsm4(uint32_t r[4], uint32_t addr) {
    asm volatile("ldmatrix.sync.aligned.m8n8.x4.shared.b16 {%0,%1,%2,%3}, [%4];"
                 : "=r"(r[0]), "=r"(r[1]), "=r"(r[2]), "=r"(r[3]) : "r"(addr));
}
__device__ __forceinline__ void mma_f32(float c[4], const uint32_t a[4],
                                        uint32_t b0, uint32_t b1) {
    asm volatile("mma.sync.aligned.m16n8k16.row.col.f32.f16.f16.f32 "
                 "{%0,%1,%2,%3}, {%4,%5,%6,%7}, {%8,%9}, {%0,%1,%2,%3};"
                 : "+f"(c[0]), "+f"(c[1]), "+f"(c[2]), "+f"(c[3])
                 : "r"(a[0]), "r"(a[1]), "r"(a[2]), "r"(a[3]), "r"(b0), "r"(b1));
}
__device__ __forceinline__ void mma_f16(uint32_t c[2], const uint32_t a[4],
                                        uint32_t b0, uint32_t b1) {
    asm volatile("mma.sync.aligned.m16n8k16.row.col.f16.f16.f16.f16 "
                 "{%0,%1}, {%2,%3,%4,%5}, {%6,%7}, {%0,%1};"
                 : "+r"(c[0]), "+r"(c[1])
                 : "r"(a[0]), "r"(a[1]), "r"(a[2]), "r"(a[3]), "r"(b0), "r"(b1));
}
__device__ __forceinline__ void cpasync16(uint32_t dst, const void* src) {
    asm volatile("cp.async.cg.shared.global [%0], [%1], 16;" :: "r"(dst), "l"(src) : "memory");
}
#define CP_COMMIT() asm volatile("cp.async.commit_group;" ::: "memory")
#define CP_WAIT(n)  asm volatile("cp.async.wait_group %0;" :: "n"(n) : "memory")

// fp32 -> (hi, style-combined second plane)
template<bool BSTYLE>
__device__ __forceinline__ void style1(float x, h16& H, h16& P) {
    const __half h = __float2half_rn(x);
    const float hf = __half2float(h);
    const float lf = x - hf;
    H = h;
    P = BSTYLE ? __float2half_rn(hf + lf * SINV)
               : __float2half_rn(lf + hf * SVAL);
}
template<bool BSTYLE>
__device__ __forceinline__ void style4(const float4& f, uint2& H, uint2& P) {
    __half2 h01, h23, p01, p23;
    style1<BSTYLE>(f.x, h01.x, p01.x);
    style1<BSTYLE>(f.y, h01.y, p01.y);
    style1<BSTYLE>(f.z, h23.x, p23.x);
    style1<BSTYLE>(f.w, h23.y, p23.y);
    H.x = *reinterpret_cast<uint32_t*>(&h01);
    H.y = *reinterpret_cast<uint32_t*>(&h23);
    P.x = *reinterpret_cast<uint32_t*>(&p01);
    P.y = *reinterpret_cast<uint32_t*>(&p23);
}

// ---------------- elementwise converter ----------------
template<bool BSTYLE>
__global__ void __launch_bounds__(256)
cvt_style(const float* __restrict__ a, const float* __restrict__ b,
          h16* __restrict__ hi, h16* __restrict__ p2)
{
    const size_t i4 = ((size_t)blockIdx.x * 256 + threadIdx.x) * 4;
    float4 f = *(const float4*)(a + i4);
    if (b) {
        const float4 e = *(const float4*)(b + i4);
        f.x += e.x; f.y += e.y; f.z += e.z; f.w += e.w;
    }
    uint2 H, P;
    style4<BSTYLE>(f, H, P);
    *(uint2*)(hi + i4) = H;
    *(uint2*)(p2 + i4) = P;
}

// ---------------- HMMA GEMM: C[M,N] = op( A[M,K] @ B[N,K]^T ) -----------------
// 512 threads, 16 warps in 4x4 grid, warp tile 32x32. CTA tile 128x128, K-chunk 64.
// Two MMAs per fragment pair: D1 = Ah*Bh (f32 acc), P = A'*B' (f16 acc).
// C = (1-s)*D1 + P. Stage 64KB: Ah | A2 | Bh | B2, SW128. NS=3 cp.async.
#define NS 3
#define PLANE_BYTES 16384
#define STAGE_BYTES 65536
#define EPI_PITCH   132
#define SMEM_TOTAL  (NS*STAGE_BYTES)    // 196608
#define NTHR 512

template<int OP, bool OUTF, bool OUTB, bool TRANS, bool OSTYLE>
__global__ void __launch_bounds__(NTHR)
hmma_gemm(const h16* __restrict__ Ahi, const h16* __restrict__ A2,
          const h16* __restrict__ Bhi, const h16* __restrict__ B2,
          const float* __restrict__ bias,
          float* __restrict__ Cf, h16* __restrict__ Chi, h16* __restrict__ C2,
          int K, int ldC, size_t sA, size_t sB, size_t sC, float scale)
{
    extern __shared__ char smem[];
    const uint32_t sbase = smem_u32(smem);

    const int t = threadIdx.x;
    const int w = t >> 5, lane = t & 31;
    const int wm = w >> 2, wn = w & 3;            // warp grid 4 x 4

    const int bz = blockIdx.z;
    Ahi += (size_t)bz * sA;  A2 += (size_t)bz * sA;
    Bhi += (size_t)bz * sB;  B2 += (size_t)bz * sB;
    const int mBase = blockIdx.y * 128;
    const int nBase = blockIdx.x * 128;

    float    accF[2][4][4];
    uint32_t accP[2][4][2];
    #pragma unroll
    for (int mi = 0; mi < 2; mi++)
        #pragma unroll
        for (int nj = 0; nj < 4; nj++) {
            #pragma unroll
            for (int e = 0; e < 4; e++) accF[mi][nj][e] = 0.f;
            accP[mi][nj][0] = 0u; accP[mi][nj][1] = 0u;
        }

    const int nk = K >> 6;

    // cp.async mapping: row = t>>2 (0..127), (t&3) selects 2 of 8 16B-chunks
    const int srow = t >> 2;
    const uint32_t srx = ((uint32_t)(srow & 7)) << 4;
    const uint32_t srowoff = (uint32_t)srow * 128;
    const size_t gArow = (size_t)(mBase + srow) * K;
    const size_t gBrow = (size_t)(nBase + srow) * K;

    auto ISSUE = [&](int kc, int s) {
        const int kb = kc << 6;
        const uint32_t st = sbase + (uint32_t)s * STAGE_BYTES;
        #pragma unroll
        for (int c = 0; c < 2; c++) {
            const int col16 = (t & 3) * 2 + c;
            const uint32_t d = srowoff + (((uint32_t)col16 * 16) ^ srx);
            const int kk = kb + col16 * 8;
            cpasync16(st + d,                 Ahi + gArow + kk);
            cpasync16(st +   PLANE_BYTES + d, A2  + gArow + kk);
            cpasync16(st + 2*PLANE_BYTES + d, Bhi + gBrow + kk);
            cpasync16(st + 3*PLANE_BYTES + d, B2  + gBrow + kk);
        }
    };

    // ldmatrix addressing
    const uint32_t arow128 = (uint32_t)(wm * 32 + (lane & 15)) * 128;
    const uint32_t a16     = ((uint32_t)(lane >> 4)) << 4;
    const uint32_t axor    = ((uint32_t)(lane & 7)) << 4;
    const uint32_t brow128 = (uint32_t)(wn * 32 + ((lane >> 4) << 3) + (lane & 7)) * 128;
    const uint32_t b16     = ((uint32_t)((lane >> 3) & 1)) << 4;

    auto COMPUTE = [&](int s) {
        const uint32_t stAh = sbase + (uint32_t)s * STAGE_BYTES;
        const uint32_t stA2 = stAh +   PLANE_BYTES;
        const uint32_t stBh = stAh + 2*PLANE_BYTES;
        const uint32_t stB2 = stAh + 3*PLANE_BYTES;
        #pragma unroll
        for (int ki = 0; ki < 4; ki++) {
            const uint32_t kba = (uint32_t)(ki * 32);
            uint32_t Ah[2][4], Ap[2][4], Bh[4][2], Bp[4][2];
            #pragma unroll
            for (int mi = 0; mi < 2; mi++) {
                ldsm4(Ah[mi], stAh + arow128 + mi * 2048 + ((kba + a16) ^ axor));
                ldsm4(Ap[mi], stA2 + arow128 + mi * 2048 + ((kba + a16) ^ axor));
            }
            #pragma unroll
            for (int nx = 0; nx < 2; nx++) {
                uint32_t tb[4];
                ldsm4(tb, stBh + brow128 + nx * 2048 + ((kba + b16) ^ axor));
                Bh[nx*2][0]   = tb[0]; Bh[nx*2][1]   = tb[1];
                Bh[nx*2+1][0] = tb[2]; Bh[nx*2+1][1] = tb[3];
                ldsm4(tb, stB2 + brow128 + nx * 2048 + ((kba + b16) ^ axor));
                Bp[nx*2][0]   = tb[0]; Bp[nx*2][1]   = tb[1];
                Bp[nx*2+1][0] = tb[2]; Bp[nx*2+1][1] = tb[3];
            }
            // main product (f32 acc), 8 independent accumulators
            #pragma unroll
            for (int nj = 0; nj < 4; nj++)
                #pragma unroll
                for (int mi = 0; mi < 2; mi++)
                    mma_f32(accF[mi][nj], Ah[mi], Bh[nj][0], Bh[nj][1]);
            // folded correction product (f16 acc)
            #pragma unroll
            for (int nj = 0; nj < 4; nj++)
                #pragma unroll
                for (int mi = 0; mi < 2; mi++)
                    mma_f16(accP[mi][nj], Ap[mi], Bp[nj][0], Bp[nj][1]);
        }
    };

    // prologue
    #pragma unroll
    for (int s = 0; s < NS - 1; s++) { ISSUE(s, s); CP_COMMIT(); }

    for (int kc = 0; kc < nk; kc++) {
        CP_WAIT(NS - 2);
        __syncthreads();
        const int kn = kc + NS - 1;
        if (kn < nk) { ISSUE(kn, kn % NS); CP_COMMIT(); }
        COMPUTE(kc % NS);
    }
    __syncthreads();

    // ---- epilogue: C = (1-s)*accF + accP; regs -> SMEM (pitch 132) -> stores
    float* epi = (float*)smem;
    const int g  = lane >> 2;
    const int tq = lane & 3;
    #pragma unroll
    for (int mi = 0; mi < 2; mi++) {
        #pragma unroll
        for (int nj = 0; nj < 4; nj++) {
            const int col = wn * 32 + nj * 8 + tq * 2;
            const __half2 c01 = *reinterpret_cast<const __half2*>(&accP[mi][nj][0]);
            const __half2 c23 = *reinterpret_cast<const __half2*>(&accP[mi][nj][1]);
            #pragma unroll
            for (int half = 0; half < 2; half++) {
                const int m = wm * 32 + mi * 16 + g + half * 8;
                const float d0 = accF[mi][nj][half*2 + 0];
                const float d1 = accF[mi][nj][half*2 + 1];
                float v0 = fmaf(-SVAL, d0, d0) + (half ? __half2float(c23.x) : __half2float(c01.x));
                float v1 = fmaf(-SVAL, d1, d1) + (half ? __half2float(c23.y) : __half2float(c01.y));
                if (OP == 2) {
                    v0 = 1.f / (1.f + __expf(-v0 * scale));
                    v1 = 1.f / (1.f + __expf(-v1 * scale));
                } else {
                    if (bias) { v0 += bias[nBase + col]; v1 += bias[nBase + col + 1]; }
                    if (OP == 1) { v0 = fmaxf(v0, 0.f); v1 = fmaxf(v1, 0.f); }
                }
                if (TRANS) {
                    epi[(col)     * EPI_PITCH + m] = v0;
                    epi[(col + 1) * EPI_PITCH + m] = v1;
                } else {
                    epi[m * EPI_PITCH + col]     = v0;
                    epi[m * EPI_PITCH + col + 1] = v1;
                }
            }
        }
    }
    __syncthreads();

    const int r  = t >> 2;
    const int ch = (t & 3) * 32;
    size_t rowOff;
    if (TRANS) {
        const size_t boffs = (size_t)(mBase >> 12) * ((size_t)EMB * SEQ);
        rowOff = boffs + (size_t)(nBase + r) * SEQ + (size_t)(mBase & (SEQ - 1)) + ch;
    } else {
        rowOff = (size_t)bz * sC + (size_t)(mBase + r) * ldC + nBase + ch;
    }
    #pragma unroll
    for (int i = 0; i < 8; i++) {
        const float* e = &epi[r * EPI_PITCH + ch + i * 4];
        const float4 f = make_float4(e[0], e[1], e[2], e[3]);
        if (OUTF) *(float4*)(Cf + rowOff + i * 4) = f;
        if (OUTB) {
            uint2 H, P;
            style4<OSTYLE>(f, H, P);
            *(uint2*)(Chi + rowOff + i * 4) = H;
            *(uint2*)(C2  + rowOff + i * 4) = P;
        }
    }
}

// ---------------- LayerNorm ----------------
template<int BF>
__global__ void __launch_bounds__(256)
layernorm_kernel(const float* __restrict__ x, const float* __restrict__ g,
                 const float* __restrict__ b, float* __restrict__ outf,
                 h16* __restrict__ ohi, h16* __restrict__ o2)
{
    const int row = blockIdx.x;
    const float* xr = x + (size_t)row * EMB;
    const int t = threadIdx.x;

    const float4 v = *(const float4*)(xr + t * 4);
    float s  = v.x + v.y + v.z + v.w;
    float ss = v.x * v.x + v.y * v.y + v.z * v.z + v.w * v.w;

    __shared__ float shs[8], shss[8], shmu[1], shinv[1];
    const int lane = t & 31, w = t >> 5;
    #pragma unroll
    for (int o = 16; o > 0; o >>= 1) {
        s  += __shfl_down_sync(0xffffffffu, s,  o);
        ss += __shfl_down_sync(0xffffffffu, ss, o);
    }
    if (lane == 0) { shs[w] = s; shss[w] = ss; }
    __syncthreads();
    if (w == 0) {
        float s2  = (lane < 8) ? shs[lane]  : 0.f;
        float ss2 = (lane < 8) ? shss[lane] : 0.f;
        #pragma unroll
        for (int o = 4; o > 0; o >>= 1) {
            s2  += __shfl_down_sync(0xffffffffu, s2,  o);
            ss2 += __shfl_down_sync(0xffffffffu, ss2, o);
        }
        if (lane == 0) {
            const float mu  = s2 * (1.f / EMB);
            const float var = ss2 * (1.f / EMB) - mu * mu;
            shmu[0]  = mu;
            shinv[0] = rsqrtf(var + 1e-5f);
        }
    }
    __syncthreads();
    const float mu = shmu[0], inv = shinv[0];

    const float4 gv = *(const float4*)(g + t * 4);
    const float4 bv = *(const float4*)(b + t * 4);
    float4 o;
    o.x = (v.x - mu) * inv * gv.x + bv.x;
    o.y = (v.y - mu) * inv * gv.y + bv.y;
    o.z = (v.z - mu) * inv * gv.z + bv.z;
    o.w = (v.w - mu) * inv * gv.w + bv.w;
    const size_t off = (size_t)row * EMB + t * 4;
    if (BF == 0) {
        *(float4*)(outf + off) = o;
    } else {
        uint2 H, P;
        style4<false>(o, H, P);
        *(uint2*)(ohi + off) = H;
        *(uint2*)(o2  + off) = P;
    }
}

// ---------------- launch ----------------
extern "C" void kernel_launch(void* const* d_in, const int* in_sizes, int n_in,
                              void* d_out, int out_size)
{
    const float* value  = (const float*)d_in[0];
    const float* key_t  = (const float*)d_in[1];
    const float* query  = (const float*)d_in[2];
    const float* embed0 = (const float*)d_in[3];
    const float* Wq = (const float*)d_in[4];
    const float* bq = (const float*)d_in[5];
    const float* Wk = (const float*)d_in[6];
    const float* bk = (const float*)d_in[7];
    const float* Wv = (const float*)d_in[8];
    const float* bv = (const float*)d_in[9];
    const float* W1 = (const float*)d_in[10];
    const float* b1 = (const float*)d_in[11];
    const float* W2 = (const float*)d_in[12];
    const float* b2 = (const float*)d_in[13];
    const float* g1  = (const float*)d_in[14];
    const float* be1 = (const float*)d_in[15];
    const float* g2  = (const float*)d_in[16];
    const float* be2 = (const float*)d_in[17];

    h16 *p_qinh, *p_qin2, *p_kinh, *p_kin2, *p_vinh, *p_vin2;
    h16 *p_wqh, *p_wq2, *p_wkh, *p_wk2, *p_wvh, *p_wv2, *p_w1h, *p_w12, *p_w2h, *p_w22;
    h16 *p_qh, *p_q2, *p_kh, *p_k2, *p_vth, *p_vt2, *p_ath, *p_at2, *p_xh, *p_x2, *p_hh, *p_h2;
    float *p_attnf, *p_x, *p_y;
    cudaGetSymbolAddress((void**)&p_qinh, qin_h); cudaGetSymbolAddress((void**)&p_qin2, qin_2);
    cudaGetSymbolAddress((void**)&p_kinh, kin_h); cudaGetSymbolAddress((void**)&p_kin2, kin_2);
    cudaGetSymbolAddress((void**)&p_vinh, vin_h); cudaGetSymbolAddress((void**)&p_vin2, vin_2);
    cudaGetSymbolAddress((void**)&p_wqh, wq_h);   cudaGetSymbolAddress((void**)&p_wq2, wq_2);
    cudaGetSymbolAddress((void**)&p_wkh, wk_h);   cudaGetSymbolAddress((void**)&p_wk2, wk_2);
    cudaGetSymbolAddress((void**)&p_wvh, wv_h);   cudaGetSymbolAddress((void**)&p_wv2, wv_2);
    cudaGetSymbolAddress((void**)&p_w1h, w1_h);   cudaGetSymbolAddress((void**)&p_w12, w1_2);
    cudaGetSymbolAddress((void**)&p_w2h, w2_h);   cudaGetSymbolAddress((void**)&p_w22, w2_2);
    cudaGetSymbolAddress((void**)&p_qh, q_h);     cudaGetSymbolAddress((void**)&p_q2, q_2);
    cudaGetSymbolAddress((void**)&p_kh, k_h);     cudaGetSymbolAddress((void**)&p_k2, k_2);
    cudaGetSymbolAddress((void**)&p_vth, vt_h);   cudaGetSymbolAddress((void**)&p_vt2, vt_2);
    cudaGetSymbolAddress((void**)&p_ath, at_h);   cudaGetSymbolAddress((void**)&p_at2, at_2);
    cudaGetSymbolAddress((void**)&p_xh, x_h);     cudaGetSymbolAddress((void**)&p_x2, x_2);
    cudaGetSymbolAddress((void**)&p_hh, h_h);     cudaGetSymbolAddress((void**)&p_h2, h_2);
    cudaGetSymbolAddress((void**)&p_attnf, g_attnf);
    cudaGetSymbolAddress((void**)&p_x, g_x);
    cudaGetSymbolAddress((void**)&p_y, g_y);

    #define SET_SMEM(KER) cudaFuncSetAttribute(KER, cudaFuncAttributeMaxDynamicSharedMemorySize, SMEM_TOTAL)
    SET_SMEM((hmma_gemm<0,false,true,false,false>));   // q out (A-style)
    SET_SMEM((hmma_gemm<0,false,true,false,true>));    // k out (B-style)
    SET_SMEM((hmma_gemm<0,false,true,true,true>));     // vt out (B-style, TRANS)
    SET_SMEM((hmma_gemm<2,true,true,false,false>));    // attn (fp32 + A-style)
    SET_SMEM((hmma_gemm<0,true,false,false,false>));   // attnV / FFN2 (fp32)
    SET_SMEM((hmma_gemm<1,false,true,false,false>));   // FFN1 (A-style)

    float* outp = (float*)d_out;
    const long long outElems  = (long long)MROWS * EMB;
    const long long attnElems = (long long)NBATCH * SEQ * SEQ;
    float* attnf = ((long long)out_size >= outElems + attnElems) ? (outp + outElems) : p_attnf;

    dim3 blk(NTHR);
    dim3 blkc(256);
    const float scale = 1.0f / 32.0f;
    const size_t sQK = (size_t)SEQ * EMB;
    const size_t sAT = (size_t)SEQ * SEQ;
    const size_t sVT = (size_t)EMB * SEQ;

    // 0) input/weight conversions
    cvt_style<false><<<MROWS*EMB/1024, blkc>>>(query, embed0, p_qinh, p_qin2);
    cvt_style<false><<<MROWS*EMB/1024, blkc>>>(key_t, embed0, p_kinh, p_kin2);
    cvt_style<false><<<MROWS*EMB/1024, blkc>>>(value, embed0, p_vinh, p_vin2);
    cvt_style<true><<<EMB*EMB/1024,   blkc>>>(Wq, nullptr, p_wqh, p_wq2);
    cvt_style<true><<<EMB*EMB/1024,   blkc>>>(Wk, nullptr, p_wkh, p_wk2);
    cvt_style<true><<<EMB*EMB/1024,   blkc>>>(Wv, nullptr, p_wvh, p_wv2);
    cvt_style<true><<<FFDIM*EMB/1024, blkc>>>(W1, nullptr, p_w1h, p_w12);
    cvt_style<true><<<EMB*FFDIM/1024, blkc>>>(W2, nullptr, p_w2h, p_w22);

    // 1) QKV projections (q A-style, k B-style, vt B-style transposed)
    dim3 gQKV(EMB / 128, MROWS / 128, 1);
    hmma_gemm<0,false,true,false,false><<<gQKV, blk, SMEM_TOTAL>>>(
        p_qinh, p_qin2, p_wqh, p_wq2, bq, nullptr, p_qh, p_q2, EMB, EMB, 0, 0, 0, 0.f);
    hmma_gemm<0,false,true,false,true><<<gQKV, blk, SMEM_TOTAL>>>(
        p_kinh, p_kin2, p_wkh, p_wk2, bk, nullptr, p_kh, p_k2, EMB, EMB, 0, 0, 0, 0.f);
    hmma_gemm<0,false,true,true,true><<<gQKV, blk, SMEM_TOTAL>>>(
        p_vinh, p_vin2, p_wvh, p_wv2, bv, nullptr, p_vth, p_vt2, EMB, SEQ, 0, 0, 0, 0.f);

    // 2) attn = sigmoid(q @ k^T * scale): fp32 output + A-style planes
    dim3 gS(SEQ / 128, SEQ / 128, NBATCH);
    hmma_gemm<2,true,true,false,false><<<gS, blk, SMEM_TOTAL>>>(
        p_qh, p_q2, p_kh, p_k2, nullptr, attnf, p_ath, p_at2, EMB, SEQ, sQK, sQK, sAT, scale);

    // 3) x = attn @ v (B = V^T B-style planes)
    dim3 gAV(EMB / 128, SEQ / 128, NBATCH);
    hmma_gemm<0,true,false,false,false><<<gAV, blk, SMEM_TOTAL>>>(
        p_ath, p_at2, p_vth, p_vt2, nullptr, p_x, nullptr, nullptr, SEQ, EMB, sAT, sVT, sQK, 0.f);

    // 4) LN1 -> A-style planes
    layernorm_kernel<1><<<MROWS, 256>>>(p_x, g1, be1, nullptr, p_xh, p_x2);

    // 5) FFN1 = relu(x @ W1^T + b1) -> A-style planes
    dim3 gF1(FFDIM / 128, MROWS / 128, 1);
    hmma_gemm<1,false,true,false,false><<<gF1, blk, SMEM_TOTAL>>>(
        p_xh, p_x2, p_w1h, p_w12, b1, nullptr, p_hh, p_h2, EMB, FFDIM, 0, 0, 0, 0.f);

    // 6) FFN2 = h @ W2^T + b2 -> fp32
    dim3 gF2(EMB / 128, MROWS / 128, 1);
    hmma_gemm<0,true,false,false,false><<<gF2, blk, SMEM_TOTAL>>>(
        p_hh, p_h2, p_w2h, p_w22, b2, p_y, nullptr, nullptr, FFDIM, EMB, 0, 0, 0, 0.f);

    // 7) LN2 -> out
    layernorm_kernel<0><<<MROWS, 256>>>(p_y, g2, be2, outp, nullptr, nullptr);
}

// round 11
// speedup vs baseline: 1.3678x; 1.3678x over previous
#include <cuda_runtime.h>
#include <cuda_fp16.h>
#include <cstdint>
#include <math.h>

#define NBATCH 2
#define SEQ    4096
#define EMB    1024
#define FFDIM  4096
#define MROWS  (NBATCH*SEQ)   // 8192

#define SVAL 0.00390625f      // s = 2^-8
#define SINV 256.0f           // 1/s

typedef __half h16;

// ---------------- scratch (device globals; allocation-free) ----------------
__device__ h16 qin_h[MROWS*EMB], qin_2[MROWS*EMB];      // A-style
__device__ h16 kin_h[MROWS*EMB], kin_2[MROWS*EMB];      // A-style
__device__ h16 vin_h[MROWS*EMB], vin_2[MROWS*EMB];      // A-style
__device__ h16 wq_h[EMB*EMB],   wq_2[EMB*EMB];          // B-style
__device__ h16 wk_h[EMB*EMB],   wk_2[EMB*EMB];          // B-style
__device__ h16 wv_h[EMB*EMB],   wv_2[EMB*EMB];          // B-style
__device__ h16 w1_h[FFDIM*EMB], w1_2[FFDIM*EMB];        // B-style
__device__ h16 w2_h[EMB*FFDIM], w2_2[EMB*FFDIM];        // B-style
__device__ h16 q_h[MROWS*EMB],  q_2[MROWS*EMB];         // A-style
__device__ h16 k_h[MROWS*EMB],  k_2[MROWS*EMB];         // B-style
__device__ h16 vt_h[NBATCH*EMB*SEQ], vt_2[NBATCH*EMB*SEQ];  // B-style
__device__ h16 at_h[(size_t)NBATCH*SEQ*SEQ], at_2[(size_t)NBATCH*SEQ*SEQ]; // A-style
__device__ h16 x_h[MROWS*EMB],  x_2[MROWS*EMB];         // A-style
__device__ h16 h_h[MROWS*FFDIM], h_2[MROWS*FFDIM];      // A-style
__device__ float g_attnf[(size_t)NBATCH*SEQ*SEQ];
__device__ float g_x[MROWS*EMB];
__device__ float g_y[MROWS*EMB];

// ---------------- helpers ----------------
__device__ __forceinline__ uint32_t smem_u32(const void* p) {
    uint32_t a;
    asm("{ .reg .u64 t; cvta.to.shared.u64 t, %1; cvt.u32.u64 %0, t; }" : "=r"(a) : "l"(p));
    return a;
}
__device__ __forceinline__ void ldsm4(uint32_t r[4], uint32_t addr) {
    asm volatile("ldmatrix.sync.aligned.m8n8.x4.shared.b16 {%0,%1,%2,%3}, [%4];"
                 : "=r"(r[0]), "=r"(r[1]), "=r"(r[2]), "=r"(r[3]) : "r"(addr));
}
__device__ __forceinline__ void mma_f32(float c[4], const uint32_t a[4],
                                        uint32_t b0, uint32_t b1) {
    asm volatile("mma.sync.aligned.m16n8k16.row.col.f32.f16.f16.f32 "
                 "{%0,%1,%2,%3}, {%4,%5,%6,%7}, {%8,%9}, {%0,%1,%2,%3};"
                 : "+f"(c[0]), "+f"(c[1]), "+f"(c[2]), "+f"(c[3])
                 : "r"(a[0]), "r"(a[1]), "r"(a[2]), "r"(a[3]), "r"(b0), "r"(b1));
}
__device__ __forceinline__ void mma_f16(uint32_t c[2], const uint32_t a[4],
                                        uint32_t b0, uint32_t b1) {
    asm volatile("mma.sync.aligned.m16n8k16.row.col.f16.f16.f16.f16 "
                 "{%0,%1}, {%2,%3,%4,%5}, {%6,%7}, {%0,%1};"
                 : "+r"(c[0]), "+r"(c[1])
                 : "r"(a[0]), "r"(a[1]), "r"(a[2]), "r"(a[3]), "r"(b0), "r"(b1));
}
__device__ __forceinline__ void cpasync16(uint32_t dst, const void* src) {
    asm volatile("cp.async.cg.shared.global [%0], [%1], 16;" :: "r"(dst), "l"(src) : "memory");
}
#define CP_COMMIT() asm volatile("cp.async.commit_group;" ::: "memory")
#define CP_WAIT(n)  asm volatile("cp.async.wait_group %0;" :: "n"(n) : "memory")

// fp32 -> (hi, style-combined second plane)
template<bool BSTYLE>
__device__ __forceinline__ void style1(float x, h16& H, h16& P) {
    const __half h = __float2half_rn(x);
    const float hf = __half2float(h);
    const float lf = x - hf;
    H = h;
    P = BSTYLE ? __float2half_rn(hf + lf * SINV)
               : __float2half_rn(lf + hf * SVAL);
}
template<bool BSTYLE>
__device__ __forceinline__ void style4(const float4& f, uint2& H, uint2& P) {
    __half2 h01, h23, p01, p23;
    style1<BSTYLE>(f.x, h01.x, p01.x);
    style1<BSTYLE>(f.y, h01.y, p01.y);
    style1<BSTYLE>(f.z, h23.x, p23.x);
    style1<BSTYLE>(f.w, h23.y, p23.y);
    H.x = *reinterpret_cast<uint32_t*>(&h01);
    H.y = *reinterpret_cast<uint32_t*>(&h23);
    P.x = *reinterpret_cast<uint32_t*>(&p01);
    P.y = *reinterpret_cast<uint32_t*>(&p23);
}

// ---------------- elementwise converter ----------------
template<bool BSTYLE>
__global__ void __launch_bounds__(256)
cvt_style(const float* __restrict__ a, const float* __restrict__ b,
          h16* __restrict__ hi, h16* __restrict__ p2)
{
    const size_t i4 = ((size_t)blockIdx.x * 256 + threadIdx.x) * 4;
    float4 f = *(const float4*)(a + i4);
    if (b) {
        const float4 e = *(const float4*)(b + i4);
        f.x += e.x; f.y += e.y; f.z += e.z; f.w += e.w;
    }
    uint2 H, P;
    style4<BSTYLE>(f, H, P);
    *(uint2*)(hi + i4) = H;
    *(uint2*)(p2 + i4) = P;
}

// ---------------- HMMA GEMM: C[M,N] = op( A[M,K] @ B[N,K]^T ) -----------------
// CTA tile 256x128, 512 threads, 16 warps 4x4, warp tile 64x32. K-chunk 64.
// Planes: Ah | A2 (A-style) | Bh | B2 (B-style).
// D1 = Ah*Bh (f32 acc); P = A2*B2 (f16 acc); C = (1-s)*D1 + P.
// Stage 96KB: Ah(32K) | A2(32K) | Bh(16K) | B2(16K), SW128. NS=2 cp.async.
#define NS 2
#define A_PLANE 32768
#define B_PLANE 16384
#define STAGE_BYTES 98304
#define EPI_PITCH   132
#define EPI_PITCH_T 260
#define SMEM_TOTAL  (NS*STAGE_BYTES)    // 196608
#define NTHR 512

template<int OP, bool OUTF, bool OUTB, bool TRANS, bool OSTYLE>
__global__ void __launch_bounds__(NTHR)
hmma_gemm(const h16* __restrict__ Ahi, const h16* __restrict__ A2,
          const h16* __restrict__ Bhi, const h16* __restrict__ B2,
          const float* __restrict__ bias,
          float* __restrict__ Cf, h16* __restrict__ Chi, h16* __restrict__ C2,
          int K, int ldC, size_t sA, size_t sB, size_t sC, float scale)
{
    extern __shared__ char smem[];
    const uint32_t sbase = smem_u32(smem);

    const int t = threadIdx.x;
    const int w = t >> 5, lane = t & 31;
    const int wm = w >> 2, wn = w & 3;            // warp grid 4 x 4

    const int bz = blockIdx.z;
    Ahi += (size_t)bz * sA;  A2 += (size_t)bz * sA;
    Bhi += (size_t)bz * sB;  B2 += (size_t)bz * sB;
    const int mBase = blockIdx.y * 256;
    const int nBase = blockIdx.x * 128;

    float    accF[4][4][4];
    uint32_t accP[4][4][2];
    #pragma unroll
    for (int mi = 0; mi < 4; mi++)
        #pragma unroll
        for (int nj = 0; nj < 4; nj++) {
            #pragma unroll
            for (int e = 0; e < 4; e++) accF[mi][nj][e] = 0.f;
            accP[mi][nj][0] = 0u; accP[mi][nj][1] = 0u;
        }

    const int nk = K >> 6;

    // cp.async mapping
    // A planes: 256 rows x 8 chunks -> row = t>>1, chunks (t&1)*4 + c (c 0..3)
    // B planes: 128 rows x 8 chunks -> row = t>>2, chunks (t&3)*2 + c (c 0..1)
    const int arow = t >> 1;
    const uint32_t arx = ((uint32_t)(arow & 7)) << 4;
    const uint32_t arowoff = (uint32_t)arow * 128;
    const int brow = t >> 2;
    const uint32_t brx = ((uint32_t)(brow & 7)) << 4;
    const uint32_t browoff = (uint32_t)brow * 128;
    const size_t gArow = (size_t)(mBase + arow) * K;
    const size_t gBrow = (size_t)(nBase + brow) * K;

    auto ISSUE = [&](int kc, int s) {
        const int kb = kc << 6;
        const uint32_t st = sbase + (uint32_t)s * STAGE_BYTES;
        #pragma unroll
        for (int c = 0; c < 4; c++) {
            const int col16 = (t & 1) * 4 + c;
            const uint32_t d = arowoff + (((uint32_t)col16 * 16) ^ arx);
            const int kk = kb + col16 * 8;
            cpasync16(st + d,           Ahi + gArow + kk);
            cpasync16(st + A_PLANE + d, A2  + gArow + kk);
        }
        #pragma unroll
        for (int c = 0; c < 2; c++) {
            const int col16 = (t & 3) * 2 + c;
            const uint32_t d = browoff + (((uint32_t)col16 * 16) ^ brx);
            const int kk = kb + col16 * 8;
            cpasync16(st + 2*A_PLANE + d,           Bhi + gBrow + kk);
            cpasync16(st + 2*A_PLANE + B_PLANE + d, B2  + gBrow + kk);
        }
    };

    // ldmatrix addressing
    const uint32_t arow128 = (uint32_t)(wm * 64 + (lane & 15)) * 128;
    const uint32_t a16     = ((uint32_t)(lane >> 4)) << 4;
    const uint32_t axor    = ((uint32_t)(lane & 7)) << 4;
    const uint32_t brow128 = (uint32_t)(wn * 32 + ((lane >> 4) << 3) + (lane & 7)) * 128;
    const uint32_t b16     = ((uint32_t)((lane >> 3) & 1)) << 4;

    auto COMPUTE = [&](int s) {
        const uint32_t st = sbase + (uint32_t)s * STAGE_BYTES;
        #pragma unroll
        for (int ki = 0; ki < 4; ki++) {
            const uint32_t kba = (uint32_t)(ki * 32);
            // pass 1: main product (f32 acc)
            {
                uint32_t Af[4][4], Bf[4][2];
                #pragma unroll
                for (int mi = 0; mi < 4; mi++)
                    ldsm4(Af[mi], st + arow128 + mi * 2048 + ((kba + a16) ^ axor));
                #pragma unroll
                for (int nx = 0; nx < 2; nx++) {
                    uint32_t tb[4];
                    ldsm4(tb, st + 2*A_PLANE + brow128 + nx * 2048 + ((kba + b16) ^ axor));
                    Bf[nx*2][0]   = tb[0]; Bf[nx*2][1]   = tb[1];
                    Bf[nx*2+1][0] = tb[2]; Bf[nx*2+1][1] = tb[3];
                }
                #pragma unroll
                for (int nj = 0; nj < 4; nj++)
                    #pragma unroll
                    for (int mi = 0; mi < 4; mi++)
                        mma_f32(accF[mi][nj], Af[mi], Bf[nj][0], Bf[nj][1]);
            }
            // pass 2: folded correction product (f16 acc)
            {
                uint32_t Af[4][4], Bf[4][2];
                #pragma unroll
                for (int mi = 0; mi < 4; mi++)
                    ldsm4(Af[mi], st + A_PLANE + arow128 + mi * 2048 + ((kba + a16) ^ axor));
                #pragma unroll
                for (int nx = 0; nx < 2; nx++) {
                    uint32_t tb[4];
                    ldsm4(tb, st + 2*A_PLANE + B_PLANE + brow128 + nx * 2048 + ((kba + b16) ^ axor));
                    Bf[nx*2][0]   = tb[0]; Bf[nx*2][1]   = tb[1];
                    Bf[nx*2+1][0] = tb[2]; Bf[nx*2+1][1] = tb[3];
                }
                #pragma unroll
                for (int nj = 0; nj < 4; nj++)
                    #pragma unroll
                    for (int mi = 0; mi < 4; mi++)
                        mma_f16(accP[mi][nj], Af[mi], Bf[nj][0], Bf[nj][1]);
            }
        }
    };

    // NS=2 pipeline
    ISSUE(0, 0);
    CP_COMMIT();
    for (int kc = 0; kc < nk; kc++) {
        CP_WAIT(0);
        __syncthreads();
        if (kc + 1 < nk) { ISSUE(kc + 1, (kc + 1) & 1); CP_COMMIT(); }
        COMPUTE(kc & 1);
    }
    __syncthreads();

    // ---- epilogue: C = (1-s)*accF + accP
    float* epi = (float*)smem;
    const int g  = lane >> 2;
    const int tq = lane & 3;
    #pragma unroll
    for (int mi = 0; mi < 4; mi++) {
        #pragma unroll
        for (int nj = 0; nj < 4; nj++) {
            const int col = wn * 32 + nj * 8 + tq * 2;
            const __half2 c01 = *reinterpret_cast<const __half2*>(&accP[mi][nj][0]);
            const __half2 c23 = *reinterpret_cast<const __half2*>(&accP[mi][nj][1]);
            #pragma unroll
            for (int half = 0; half < 2; half++) {
                const int m = wm * 64 + mi * 16 + g + half * 8;
                const float d0 = accF[mi][nj][half*2 + 0];
                const float d1 = accF[mi][nj][half*2 + 1];
                float v0 = fmaf(-SVAL, d0, d0) + (half ? __half2float(c23.x) : __half2float(c01.x));
                float v1 = fmaf(-SVAL, d1, d1) + (half ? __half2float(c23.y) : __half2float(c01.y));
                if (OP == 2) {
                    v0 = 1.f / (1.f + __expf(-v0 * scale));
                    v1 = 1.f / (1.f + __expf(-v1 * scale));
                } else {
                    if (bias) { v0 += bias[nBase + col]; v1 += bias[nBase + col + 1]; }
                    if (OP == 1) { v0 = fmaxf(v0, 0.f); v1 = fmaxf(v1, 0.f); }
                }
                if (TRANS) {
                    epi[(col)     * EPI_PITCH_T + m] = v0;
                    epi[(col + 1) * EPI_PITCH_T + m] = v1;
                } else {
                    epi[m * EPI_PITCH + col]     = v0;
                    epi[m * EPI_PITCH + col + 1] = v1;
                }
            }
        }
    }
    __syncthreads();

    if (TRANS) {
        // tile stored [n][m] (128 x 256); write C^T[batch][nGlob][mGlob], ld = SEQ
        const int r  = t >> 2;            // 0..127
        const int ch = (t & 3) * 64;      // 0..192
        const size_t boffs = (size_t)(mBase >> 12) * ((size_t)EMB * SEQ);
        const size_t rowOff = boffs + (size_t)(nBase + r) * SEQ + (size_t)(mBase & (SEQ - 1)) + ch;
        #pragma unroll
        for (int i = 0; i < 16; i++) {
            const float* e = &epi[r * EPI_PITCH_T + ch + i * 4];
            const float4 f = make_float4(e[0], e[1], e[2], e[3]);
            if (OUTF) *(float4*)(Cf + rowOff + i * 4) = f;
            if (OUTB) {
                uint2 H, P;
                style4<OSTYLE>(f, H, P);
                *(uint2*)(Chi + rowOff + i * 4) = H;
                *(uint2*)(C2  + rowOff + i * 4) = P;
            }
        }
    } else {
        const int r  = t >> 1;            // 0..255
        const int ch = (t & 1) * 64;
        const size_t rowOff = (size_t)bz * sC + (size_t)(mBase + r) * ldC + nBase + ch;
        #pragma unroll
        for (int i = 0; i < 16; i++) {
            const float* e = &epi[r * EPI_PITCH + ch + i * 4];
            const float4 f = make_float4(e[0], e[1], e[2], e[3]);
            if (OUTF) *(float4*)(Cf + rowOff + i * 4) = f;
            if (OUTB) {
                uint2 H, P;
                style4<OSTYLE>(f, H, P);
                *(uint2*)(Chi + rowOff + i * 4) = H;
                *(uint2*)(C2  + rowOff + i * 4) = P;
            }
        }
    }
}

// ---------------- LayerNorm ----------------
template<int BF>
__global__ void __launch_bounds__(256)
layernorm_kernel(const float* __restrict__ x, const float* __restrict__ g,
                 const float* __restrict__ b, float* __restrict__ outf,
                 h16* __restrict__ ohi, h16* __restrict__ o2)
{
    const int row = blockIdx.x;
    const float* xr = x + (size_t)row * EMB;
    const int t = threadIdx.x;

    const float4 v = *(const float4*)(xr + t * 4);
    float s  = v.x + v.y + v.z + v.w;
    float ss = v.x * v.x + v.y * v.y + v.z * v.z + v.w * v.w;

    __shared__ float shs[8], shss[8], shmu[1], shinv[1];
    const int lane = t & 31, w = t >> 5;
    #pragma unroll
    for (int o = 16; o > 0; o >>= 1) {
        s  += __shfl_down_sync(0xffffffffu, s,  o);
        ss += __shfl_down_sync(0xffffffffu, ss, o);
    }
    if (lane == 0) { shs[w] = s; shss[w] = ss; }
    __syncthreads();
    if (w == 0) {
        float s2  = (lane < 8) ? shs[lane]  : 0.f;
        float ss2 = (lane < 8) ? shss[lane] : 0.f;
        #pragma unroll
        for (int o = 4; o > 0; o >>= 1) {
            s2  += __shfl_down_sync(0xffffffffu, s2,  o);
            ss2 += __shfl_down_sync(0xffffffffu, ss2, o);
        }
        if (lane == 0) {
            const float mu  = s2 * (1.f / EMB);
            const float var = ss2 * (1.f / EMB) - mu * mu;
            shmu[0]  = mu;
            shinv[0] = rsqrtf(var + 1e-5f);
        }
    }
    __syncthreads();
    const float mu = shmu[0], inv = shinv[0];

    const float4 gv = *(const float4*)(g + t * 4);
    const float4 bv = *(const float4*)(b + t * 4);
    float4 o;
    o.x = (v.x - mu) * inv * gv.x + bv.x;
    o.y = (v.y - mu) * inv * gv.y + bv.y;
    o.z = (v.z - mu) * inv * gv.z + bv.z;
    o.w = (v.w - mu) * inv * gv.w + bv.w;
    const size_t off = (size_t)row * EMB + t * 4;
    if (BF == 0) {
        *(float4*)(outf + off) = o;
    } else {
        uint2 H, P;
        style4<false>(o, H, P);
        *(uint2*)(ohi + off) = H;
        *(uint2*)(o2  + off) = P;
    }
}

// ---------------- launch ----------------
extern "C" void kernel_launch(void* const* d_in, const int* in_sizes, int n_in,
                              void* d_out, int out_size)
{
    const float* value  = (const float*)d_in[0];
    const float* key_t  = (const float*)d_in[1];
    const float* query  = (const float*)d_in[2];
    const float* embed0 = (const float*)d_in[3];
    const float* Wq = (const float*)d_in[4];
    const float* bq = (const float*)d_in[5];
    const float* Wk = (const float*)d_in[6];
    const float* bk = (const float*)d_in[7];
    const float* Wv = (const float*)d_in[8];
    const float* bv = (const float*)d_in[9];
    const float* W1 = (const float*)d_in[10];
    const float* b1 = (const float*)d_in[11];
    const float* W2 = (const float*)d_in[12];
    const float* b2 = (const float*)d_in[13];
    const float* g1  = (const float*)d_in[14];
    const float* be1 = (const float*)d_in[15];
    const float* g2  = (const float*)d_in[16];
    const float* be2 = (const float*)d_in[17];

    h16 *p_qinh, *p_qin2, *p_kinh, *p_kin2, *p_vinh, *p_vin2;
    h16 *p_wqh, *p_wq2, *p_wkh, *p_wk2, *p_wvh, *p_wv2, *p_w1h, *p_w12, *p_w2h, *p_w22;
    h16 *p_qh, *p_q2, *p_kh, *p_k2, *p_vth, *p_vt2, *p_ath, *p_at2, *p_xh, *p_x2, *p_hh, *p_h2;
    float *p_attnf, *p_x, *p_y;
    cudaGetSymbolAddress((void**)&p_qinh, qin_h); cudaGetSymbolAddress((void**)&p_qin2, qin_2);
    cudaGetSymbolAddress((void**)&p_kinh, kin_h); cudaGetSymbolAddress((void**)&p_kin2, kin_2);
    cudaGetSymbolAddress((void**)&p_vinh, vin_h); cudaGetSymbolAddress((void**)&p_vin2, vin_2);
    cudaGetSymbolAddress((void**)&p_wqh, wq_h);   cudaGetSymbolAddress((void**)&p_wq2, wq_2);
    cudaGetSymbolAddress((void**)&p_wkh, wk_h);   cudaGetSymbolAddress((void**)&p_wk2, wk_2);
    cudaGetSymbolAddress((void**)&p_wvh, wv_h);   cudaGetSymbolAddress((void**)&p_wv2, wv_2);
    cudaGetSymbolAddress((void**)&p_w1h, w1_h);   cudaGetSymbolAddress((void**)&p_w12, w1_2);
    cudaGetSymbolAddress((void**)&p_w2h, w2_h);   cudaGetSymbolAddress((void**)&p_w22, w2_2);
    cudaGetSymbolAddress((void**)&p_qh, q_h);     cudaGetSymbolAddress((void**)&p_q2, q_2);
    cudaGetSymbolAddress((void**)&p_kh, k_h);     cudaGetSymbolAddress((void**)&p_k2, k_2);
    cudaGetSymbolAddress((void**)&p_vth, vt_h);   cudaGetSymbolAddress((void**)&p_vt2, vt_2);
    cudaGetSymbolAddress((void**)&p_ath, at_h);   cudaGetSymbolAddress((void**)&p_at2, at_2);
    cudaGetSymbolAddress((void**)&p_xh, x_h);     cudaGetSymbolAddress((void**)&p_x2, x_2);
    cudaGetSymbolAddress((void**)&p_hh, h_h);     cudaGetSymbolAddress((void**)&p_h2, h_2);
    cudaGetSymbolAddress((void**)&p_attnf, g_attnf);
    cudaGetSymbolAddress((void**)&p_x, g_x);
    cudaGetSymbolAddress((void**)&p_y, g_y);

    #define SET_SMEM(KER) cudaFuncSetAttribute(KER, cudaFuncAttributeMaxDynamicSharedMemorySize, SMEM_TOTAL)
    SET_SMEM((hmma_gemm<0,false,true,false,false>));   // q out (A-style)
    SET_SMEM((hmma_gemm<0,false,true,false,true>));    // k out (B-style)
    SET_SMEM((hmma_gemm<0,false,true,true,true>));     // vt out (B-style, TRANS)
    SET_SMEM((hmma_gemm<2,true,true,false,false>));    // attn (fp32 + A-style)
    SET_SMEM((hmma_gemm<0,true,false,false,false>));   // attnV / FFN2 (fp32)
    SET_SMEM((hmma_gemm<1,false,true,false,false>));   // FFN1 (A-style)

    float* outp = (float*)d_out;
    const long long outElems  = (long long)MROWS * EMB;
    const long long attnElems = (long long)NBATCH * SEQ * SEQ;
    float* attnf = ((long long)out_size >= outElems + attnElems) ? (outp + outElems) : p_attnf;

    dim3 blk(NTHR);
    dim3 blkc(256);
    const float scale = 1.0f / 32.0f;
    const size_t sQK = (size_t)SEQ * EMB;
    const size_t sAT = (size_t)SEQ * SEQ;
    const size_t sVT = (size_t)EMB * SEQ;

    // 0) input/weight conversions
    cvt_style<false><<<MROWS*EMB/1024, blkc>>>(query, embed0, p_qinh, p_qin2);
    cvt_style<false><<<MROWS*EMB/1024, blkc>>>(key_t, embed0, p_kinh, p_kin2);
    cvt_style<false><<<MROWS*EMB/1024, blkc>>>(value, embed0, p_vinh, p_vin2);
    cvt_style<true><<<EMB*EMB/1024,   blkc>>>(Wq, nullptr, p_wqh, p_wq2);
    cvt_style<true><<<EMB*EMB/1024,   blkc>>>(Wk, nullptr, p_wkh, p_wk2);
    cvt_style<true><<<EMB*EMB/1024,   blkc>>>(Wv, nullptr, p_wvh, p_wv2);
    cvt_style<true><<<FFDIM*EMB/1024, blkc>>>(W1, nullptr, p_w1h, p_w12);
    cvt_style<true><<<EMB*FFDIM/1024, blkc>>>(W2, nullptr, p_w2h, p_w22);

    // 1) QKV projections (q A-style, k B-style, vt B-style transposed)
    dim3 gQKV(EMB / 128, MROWS / 256, 1);
    hmma_gemm<0,false,true,false,false><<<gQKV, blk, SMEM_TOTAL>>>(
        p_qinh, p_qin2, p_wqh, p_wq2, bq, nullptr, p_qh, p_q2, EMB, EMB, 0, 0, 0, 0.f);
    hmma_gemm<0,false,true,false,true><<<gQKV, blk, SMEM_TOTAL>>>(
        p_kinh, p_kin2, p_wkh, p_wk2, bk, nullptr, p_kh, p_k2, EMB, EMB, 0, 0, 0, 0.f);
    hmma_gemm<0,false,true,true,true><<<gQKV, blk, SMEM_TOTAL>>>(
        p_vinh, p_vin2, p_wvh, p_wv2, bv, nullptr, p_vth, p_vt2, EMB, SEQ, 0, 0, 0, 0.f);

    // 2) attn = sigmoid(q @ k^T * scale): fp32 output + A-style planes
    dim3 gS(SEQ / 128, SEQ / 256, NBATCH);
    hmma_gemm<2,true,true,false,false><<<gS, blk, SMEM_TOTAL>>>(
        p_qh, p_q2, p_kh, p_k2, nullptr, attnf, p_ath, p_at2, EMB, SEQ, sQK, sQK, sAT, scale);

    // 3) x = attn @ v (B = V^T B-style planes)
    dim3 gAV(EMB / 128, SEQ / 256, NBATCH);
    hmma_gemm<0,true,false,false,false><<<gAV, blk, SMEM_TOTAL>>>(
        p_ath, p_at2, p_vth, p_vt2, nullptr, p_x, nullptr, nullptr, SEQ, EMB, sAT, sVT, sQK, 0.f);

    // 4) LN1 -> A-style planes
    layernorm_kernel<1><<<MROWS, 256>>>(p_x, g1, be1, nullptr, p_xh, p_x2);

    // 5) FFN1 = relu(x @ W1^T + b1) -> A-style planes
    dim3 gF1(FFDIM / 128, MROWS / 256, 1);
    hmma_gemm<1,false,true,false,false><<<gF1, blk, SMEM_TOTAL>>>(
        p_xh, p_x2, p_w1h, p_w12, b1, nullptr, p_hh, p_h2, EMB, FFDIM, 0, 0, 0, 0.f);

    // 6) FFN2 = h @ W2^T + b2 -> fp32
    dim3 gF2(EMB / 128, MROWS / 256, 1);
    hmma_gemm<0,true,false,false,false><<<gF2, blk, SMEM_TOTAL>>>(
        p_hh, p_h2, p_w2h, p_w22, b2, p_y, nullptr, nullptr, FFDIM, EMB, 0, 0, 0, 0.f);

    // 7) LN2 -> out
    layernorm_kernel<0><<<MROWS, 256>>>(p_y, g2, be2, outp, nullptr, nullptr);
}

// round 12
// speedup vs baseline: 1.5980x; 1.1683x over previous
#include <cuda_runtime.h>
#include <cuda_fp16.h>
#include <cstdint>
#include <math.h>

#define NBATCH 2
#define SEQ    4096
#define EMB    1024
#define FFDIM  4096
#define MROWS  (NBATCH*SEQ)   // 8192

#define SVAL 0.00390625f      // s = 2^-8
#define SINV 256.0f           // 1/s

typedef __half h16;

// ---------------- scratch (device globals; allocation-free) ----------------
__device__ h16 qin_h[MROWS*EMB], qin_2[MROWS*EMB];      // A-style
__device__ h16 kin_h[MROWS*EMB], kin_2[MROWS*EMB];      // A-style
__device__ h16 vin_h[MROWS*EMB], vin_2[MROWS*EMB];      // A-style
__device__ h16 wq_h[EMB*EMB],   wq_2[EMB*EMB];          // B-style
__device__ h16 wk_h[EMB*EMB],   wk_2[EMB*EMB];          // B-style
__device__ h16 wv_h[EMB*EMB],   wv_2[EMB*EMB];          // B-style
__device__ h16 w1_h[FFDIM*EMB], w1_2[FFDIM*EMB];        // B-style
__device__ h16 w2_h[EMB*FFDIM], w2_2[EMB*FFDIM];        // B-style
__device__ h16 q_h[MROWS*EMB],  q_2[MROWS*EMB];         // A-style
__device__ h16 k_h[MROWS*EMB],  k_2[MROWS*EMB];         // B-style
__device__ h16 vt_h[NBATCH*EMB*SEQ];                    // B-side hi (no corr consumer)
__device__ h16 at_h[(size_t)NBATCH*SEQ*SEQ];            // A-side hi (no corr consumer)
__device__ h16 x_h[MROWS*EMB],  x_2[MROWS*EMB];         // A-style
__device__ h16 h_h[MROWS*FFDIM], h_2[MROWS*FFDIM];      // A-style
__device__ float g_attnf[(size_t)NBATCH*SEQ*SEQ];
__device__ float g_x[MROWS*EMB];
__device__ float g_y[MROWS*EMB];

// ---------------- helpers ----------------
__device__ __forceinline__ uint32_t smem_u32(const void* p) {
    uint32_t a;
    asm("{ .reg .u64 t; cvta.to.shared.u64 t, %1; cvt.u32.u64 %0, t; }" : "=r"(a) : "l"(p));
    return a;
}
__device__ __forceinline__ void ldsm4(uint32_t r[4], uint32_t addr) {
    asm volatile("ldmatrix.sync.aligned.m8n8.x4.shared.b16 {%0,%1,%2,%3}, [%4];"
                 : "=r"(r[0]), "=r"(r[1]), "=r"(r[2]), "=r"(r[3]) : "r"(addr));
}
__device__ __forceinline__ void mma_f32(float c[4], const uint32_t a[4],
                                        uint32_t b0, uint32_t b1) {
    asm volatile("mma.sync.aligned.m16n8k16.row.col.f32.f16.f16.f32 "
                 "{%0,%1,%2,%3}, {%4,%5,%6,%7}, {%8,%9}, {%0,%1,%2,%3};"
                 : "+f"(c[0]), "+f"(c[1]), "+f"(c[2]), "+f"(c[3])
                 : "r"(a[0]), "r"(a[1]), "r"(a[2]), "r"(a[3]), "r"(b0), "r"(b1));
}
__device__ __forceinline__ void mma_f16(uint32_t c[2], const uint32_t a[4],
                                        uint32_t b0, uint32_t b1) {
    asm volatile("mma.sync.aligned.m16n8k16.row.col.f16.f16.f16.f16 "
                 "{%0,%1}, {%2,%3,%4,%5}, {%6,%7}, {%0,%1};"
                 : "+r"(c[0]), "+r"(c[1])
                 : "r"(a[0]), "r"(a[1]), "r"(a[2]), "r"(a[3]), "r"(b0), "r"(b1));
}
__device__ __forceinline__ void cpasync16(uint32_t dst, const void* src) {
    asm volatile("cp.async.cg.shared.global [%0], [%1], 16;" :: "r"(dst), "l"(src) : "memory");
}
#define CP_COMMIT() asm volatile("cp.async.commit_group;" ::: "memory")
#define CP_WAIT(n)  asm volatile("cp.async.wait_group %0;" :: "n"(n) : "memory")

// fp32 -> (hi, style-combined second plane)
template<bool BSTYLE>
__device__ __forceinline__ void style1(float x, h16& H, h16& P) {
    const __half h = __float2half_rn(x);
    const float hf = __half2float(h);
    const float lf = x - hf;
    H = h;
    P = BSTYLE ? __float2half_rn(hf + lf * SINV)
               : __float2half_rn(lf + hf * SVAL);
}
template<bool BSTYLE>
__device__ __forceinline__ void style4(const float4& f, uint2& H, uint2& P) {
    __half2 h01, h23, p01, p23;
    style1<BSTYLE>(f.x, h01.x, p01.x);
    style1<BSTYLE>(f.y, h01.y, p01.y);
    style1<BSTYLE>(f.z, h23.x, p23.x);
    style1<BSTYLE>(f.w, h23.y, p23.y);
    H.x = *reinterpret_cast<uint32_t*>(&h01);
    H.y = *reinterpret_cast<uint32_t*>(&h23);
    P.x = *reinterpret_cast<uint32_t*>(&p01);
    P.y = *reinterpret_cast<uint32_t*>(&p23);
}

// ---------------- elementwise converter ----------------
template<bool BSTYLE>
__global__ void __launch_bounds__(256)
cvt_style(const float* __restrict__ a, const float* __restrict__ b,
          h16* __restrict__ hi, h16* __restrict__ p2)
{
    const size_t i4 = ((size_t)blockIdx.x * 256 + threadIdx.x) * 4;
    float4 f = *(const float4*)(a + i4);
    if (b) {
        const float4 e = *(const float4*)(b + i4);
        f.x += e.x; f.y += e.y; f.z += e.z; f.w += e.w;
    }
    uint2 H, P;
    style4<BSTYLE>(f, H, P);
    *(uint2*)(hi + i4) = H;
    *(uint2*)(p2 + i4) = P;
}

// ---------------- HMMA GEMM: C[M,N] = op( A[M,K] @ B[N,K]^T ) -----------------
// CTA tile 256x128, 512 threads, 16 warps 4x4, warp tile 64x32. K-chunk 64.
// CORR=true: D1 = Ah*Bh (f32 acc), P = A2*B2 (f16 acc), C = (1-s)*D1 + P.
// CORR=false: C = Ah*Bh (hi-only, half the MMA work).
// Stage 96KB: Ah(32K) | A2(32K) | Bh(16K) | B2(16K), SW128. NS=2 cp.async.
#define NS 2
#define A_PLANE 32768
#define B_PLANE 16384
#define STAGE_BYTES 98304
#define EPI_PITCH   132
#define EPI_PITCH_T 260
#define SMEM_TOTAL  (NS*STAGE_BYTES)    // 196608
#define NTHR 512

template<int OP, bool OUTF, bool OUTB, bool TRANS, bool OSTYLE, bool CORR>
__global__ void __launch_bounds__(NTHR)
hmma_gemm(const h16* __restrict__ Ahi, const h16* __restrict__ A2,
          const h16* __restrict__ Bhi, const h16* __restrict__ B2,
          const float* __restrict__ bias,
          float* __restrict__ Cf, h16* __restrict__ Chi, h16* __restrict__ C2,
          int K, int ldC, size_t sA, size_t sB, size_t sC, float scale)
{
    extern __shared__ char smem[];
    const uint32_t sbase = smem_u32(smem);

    const int t = threadIdx.x;
    const int w = t >> 5, lane = t & 31;
    const int wm = w >> 2, wn = w & 3;            // warp grid 4 x 4

    const int bz = blockIdx.z;
    Ahi += (size_t)bz * sA;  A2 += (size_t)bz * sA;
    Bhi += (size_t)bz * sB;  B2 += (size_t)bz * sB;
    const int mBase = blockIdx.y * 256;
    const int nBase = blockIdx.x * 128;

    float    accF[4][4][4];
    uint32_t accP[4][4][2];
    #pragma unroll
    for (int mi = 0; mi < 4; mi++)
        #pragma unroll
        for (int nj = 0; nj < 4; nj++) {
            #pragma unroll
            for (int e = 0; e < 4; e++) accF[mi][nj][e] = 0.f;
            accP[mi][nj][0] = 0u; accP[mi][nj][1] = 0u;
        }

    const int nk = K >> 6;

    // cp.async mapping
    const int arow = t >> 1;
    const uint32_t arx = ((uint32_t)(arow & 7)) << 4;
    const uint32_t arowoff = (uint32_t)arow * 128;
    const int brow = t >> 2;
    const uint32_t brx = ((uint32_t)(brow & 7)) << 4;
    const uint32_t browoff = (uint32_t)brow * 128;
    const size_t gArow = (size_t)(mBase + arow) * K;
    const size_t gBrow = (size_t)(nBase + brow) * K;

    auto ISSUE = [&](int kc, int s) {
        const int kb = kc << 6;
        const uint32_t st = sbase + (uint32_t)s * STAGE_BYTES;
        #pragma unroll
        for (int c = 0; c < 4; c++) {
            const int col16 = (t & 1) * 4 + c;
            const uint32_t d = arowoff + (((uint32_t)col16 * 16) ^ arx);
            const int kk = kb + col16 * 8;
            cpasync16(st + d, Ahi + gArow + kk);
            if (CORR) cpasync16(st + A_PLANE + d, A2 + gArow + kk);
        }
        #pragma unroll
        for (int c = 0; c < 2; c++) {
            const int col16 = (t & 3) * 2 + c;
            const uint32_t d = browoff + (((uint32_t)col16 * 16) ^ brx);
            const int kk = kb + col16 * 8;
            cpasync16(st + 2*A_PLANE + d, Bhi + gBrow + kk);
            if (CORR) cpasync16(st + 2*A_PLANE + B_PLANE + d, B2 + gBrow + kk);
        }
    };

    // ldmatrix addressing
    const uint32_t arow128 = (uint32_t)(wm * 64 + (lane & 15)) * 128;
    const uint32_t a16     = ((uint32_t)(lane >> 4)) << 4;
    const uint32_t axor    = ((uint32_t)(lane & 7)) << 4;
    const uint32_t brow128 = (uint32_t)(wn * 32 + ((lane >> 4) << 3) + (lane & 7)) * 128;
    const uint32_t b16     = ((uint32_t)((lane >> 3) & 1)) << 4;

    auto COMPUTE = [&](int s) {
        const uint32_t st = sbase + (uint32_t)s * STAGE_BYTES;
        #pragma unroll
        for (int ki = 0; ki < 4; ki++) {
            const uint32_t kba = (uint32_t)(ki * 32);
            // pass 1: main product (f32 acc)
            {
                uint32_t Af[4][4], Bf[4][2];
                #pragma unroll
                for (int mi = 0; mi < 4; mi++)
                    ldsm4(Af[mi], st + arow128 + mi * 2048 + ((kba + a16) ^ axor));
                #pragma unroll
                for (int nx = 0; nx < 2; nx++) {
                    uint32_t tb[4];
                    ldsm4(tb, st + 2*A_PLANE + brow128 + nx * 2048 + ((kba + b16) ^ axor));
                    Bf[nx*2][0]   = tb[0]; Bf[nx*2][1]   = tb[1];
                    Bf[nx*2+1][0] = tb[2]; Bf[nx*2+1][1] = tb[3];
                }
                #pragma unroll
                for (int nj = 0; nj < 4; nj++)
                    #pragma unroll
                    for (int mi = 0; mi < 4; mi++)
                        mma_f32(accF[mi][nj], Af[mi], Bf[nj][0], Bf[nj][1]);
            }
            // pass 2: folded correction product (f16 acc)
            if (CORR) {
                uint32_t Af[4][4], Bf[4][2];
                #pragma unroll
                for (int mi = 0; mi < 4; mi++)
                    ldsm4(Af[mi], st + A_PLANE + arow128 + mi * 2048 + ((kba + a16) ^ axor));
                #pragma unroll
                for (int nx = 0; nx < 2; nx++) {
                    uint32_t tb[4];
                    ldsm4(tb, st + 2*A_PLANE + B_PLANE + brow128 + nx * 2048 + ((kba + b16) ^ axor));
                    Bf[nx*2][0]   = tb[0]; Bf[nx*2][1]   = tb[1];
                    Bf[nx*2+1][0] = tb[2]; Bf[nx*2+1][1] = tb[3];
                }
                #pragma unroll
                for (int nj = 0; nj < 4; nj++)
                    #pragma unroll
                    for (int mi = 0; mi < 4; mi++)
                        mma_f16(accP[mi][nj], Af[mi], Bf[nj][0], Bf[nj][1]);
            }
        }
    };

    // NS=2 pipeline
    ISSUE(0, 0);
    CP_COMMIT();
    for (int kc = 0; kc < nk; kc++) {
        CP_WAIT(0);
        __syncthreads();
        if (kc + 1 < nk) { ISSUE(kc + 1, (kc + 1) & 1); CP_COMMIT(); }
        COMPUTE(kc & 1);
    }
    __syncthreads();

    // ---- epilogue
    float* epi = (float*)smem;
    const int g  = lane >> 2;
    const int tq = lane & 3;
    #pragma unroll
    for (int mi = 0; mi < 4; mi++) {
        #pragma unroll
        for (int nj = 0; nj < 4; nj++) {
            const int col = wn * 32 + nj * 8 + tq * 2;
            const __half2 c01 = *reinterpret_cast<const __half2*>(&accP[mi][nj][0]);
            const __half2 c23 = *reinterpret_cast<const __half2*>(&accP[mi][nj][1]);
            #pragma unroll
            for (int half = 0; half < 2; half++) {
                const int m = wm * 64 + mi * 16 + g + half * 8;
                const float d0 = accF[mi][nj][half*2 + 0];
                const float d1 = accF[mi][nj][half*2 + 1];
                float v0, v1;
                if (CORR) {
                    v0 = fmaf(-SVAL, d0, d0) + (half ? __half2float(c23.x) : __half2float(c01.x));
                    v1 = fmaf(-SVAL, d1, d1) + (half ? __half2float(c23.y) : __half2float(c01.y));
                } else {
                    v0 = d0; v1 = d1;
                }
                if (OP == 2) {
                    v0 = 1.f / (1.f + __expf(-v0 * scale));
                    v1 = 1.f / (1.f + __expf(-v1 * scale));
                } else {
                    if (bias) { v0 += bias[nBase + col]; v1 += bias[nBase + col + 1]; }
                    if (OP == 1) { v0 = fmaxf(v0, 0.f); v1 = fmaxf(v1, 0.f); }
                }
                if (TRANS) {
                    epi[(col)     * EPI_PITCH_T + m] = v0;
                    epi[(col + 1) * EPI_PITCH_T + m] = v1;
                } else {
                    epi[m * EPI_PITCH + col]     = v0;
                    epi[m * EPI_PITCH + col + 1] = v1;
                }
            }
        }
    }
    __syncthreads();

    if (TRANS) {
        const int r  = t >> 2;            // 0..127
        const int ch = (t & 3) * 64;      // 0..192
        const size_t boffs = (size_t)(mBase >> 12) * ((size_t)EMB * SEQ);
        const size_t rowOff = boffs + (size_t)(nBase + r) * SEQ + (size_t)(mBase & (SEQ - 1)) + ch;
        #pragma unroll
        for (int i = 0; i < 16; i++) {
            const float* e = &epi[r * EPI_PITCH_T + ch + i * 4];
            const float4 f = make_float4(e[0], e[1], e[2], e[3]);
            if (OUTF) *(float4*)(Cf + rowOff + i * 4) = f;
            if (OUTB) {
                uint2 H, P;
                style4<OSTYLE>(f, H, P);
                *(uint2*)(Chi + rowOff + i * 4) = H;
                if (C2) *(uint2*)(C2 + rowOff + i * 4) = P;
            }
        }
    } else {
        const int r  = t >> 1;            // 0..255
        const int ch = (t & 1) * 64;
        const size_t rowOff = (size_t)bz * sC + (size_t)(mBase + r) * ldC + nBase + ch;
        #pragma unroll
        for (int i = 0; i < 16; i++) {
            const float* e = &epi[r * EPI_PITCH + ch + i * 4];
            const float4 f = make_float4(e[0], e[1], e[2], e[3]);
            if (OUTF) *(float4*)(Cf + rowOff + i * 4) = f;
            if (OUTB) {
                uint2 H, P;
                style4<OSTYLE>(f, H, P);
                *(uint2*)(Chi + rowOff + i * 4) = H;
                if (C2) *(uint2*)(C2 + rowOff + i * 4) = P;
            }
        }
    }
}

// ---------------- LayerNorm ----------------
template<int BF>
__global__ void __launch_bounds__(256)
layernorm_kernel(const float* __restrict__ x, const float* __restrict__ g,
                 const float* __restrict__ b, float* __restrict__ outf,
                 h16* __restrict__ ohi, h16* __restrict__ o2)
{
    const int row = blockIdx.x;
    const float* xr = x + (size_t)row * EMB;
    const int t = threadIdx.x;

    const float4 v = *(const float4*)(xr + t * 4);
    float s  = v.x + v.y + v.z + v.w;
    float ss = v.x * v.x + v.y * v.y + v.z * v.z + v.w * v.w;

    __shared__ float shs[8], shss[8], shmu[1], shinv[1];
    const int lane = t & 31, w = t >> 5;
    #pragma unroll
    for (int o = 16; o > 0; o >>= 1) {
        s  += __shfl_down_sync(0xffffffffu, s,  o);
        ss += __shfl_down_sync(0xffffffffu, ss, o);
    }
    if (lane == 0) { shs[w] = s; shss[w] = ss; }
    __syncthreads();
    if (w == 0) {
        float s2  = (lane < 8) ? shs[lane]  : 0.f;
        float ss2 = (lane < 8) ? shss[lane] : 0.f;
        #pragma unroll
        for (int o = 4; o > 0; o >>= 1) {
            s2  += __shfl_down_sync(0xffffffffu, s2,  o);
            ss2 += __shfl_down_sync(0xffffffffu, ss2, o);
        }
        if (lane == 0) {
            const float mu  = s2 * (1.f / EMB);
            const float var = ss2 * (1.f / EMB) - mu * mu;
            shmu[0]  = mu;
            shinv[0] = rsqrtf(var + 1e-5f);
        }
    }
    __syncthreads();
    const float mu = shmu[0], inv = shinv[0];

    const float4 gv = *(const float4*)(g + t * 4);
    const float4 bv = *(const float4*)(b + t * 4);
    float4 o;
    o.x = (v.x - mu) * inv * gv.x + bv.x;
    o.y = (v.y - mu) * inv * gv.y + bv.y;
    o.z = (v.z - mu) * inv * gv.z + bv.z;
    o.w = (v.w - mu) * inv * gv.w + bv.w;
    const size_t off = (size_t)row * EMB + t * 4;
    if (BF == 0) {
        *(float4*)(outf + off) = o;
    } else {
        uint2 H, P;
        style4<false>(o, H, P);
        *(uint2*)(ohi + off) = H;
        *(uint2*)(o2  + off) = P;
    }
}

// ---------------- launch ----------------
extern "C" void kernel_launch(void* const* d_in, const int* in_sizes, int n_in,
                              void* d_out, int out_size)
{
    const float* value  = (const float*)d_in[0];
    const float* key_t  = (const float*)d_in[1];
    const float* query  = (const float*)d_in[2];
    const float* embed0 = (const float*)d_in[3];
    const float* Wq = (const float*)d_in[4];
    const float* bq = (const float*)d_in[5];
    const float* Wk = (const float*)d_in[6];
    const float* bk = (const float*)d_in[7];
    const float* Wv = (const float*)d_in[8];
    const float* bv = (const float*)d_in[9];
    const float* W1 = (const float*)d_in[10];
    const float* b1 = (const float*)d_in[11];
    const float* W2 = (const float*)d_in[12];
    const float* b2 = (const float*)d_in[13];
    const float* g1  = (const float*)d_in[14];
    const float* be1 = (const float*)d_in[15];
    const float* g2  = (const float*)d_in[16];
    const float* be2 = (const float*)d_in[17];

    h16 *p_qinh, *p_qin2, *p_kinh, *p_kin2, *p_vinh, *p_vin2;
    h16 *p_wqh, *p_wq2, *p_wkh, *p_wk2, *p_wvh, *p_wv2, *p_w1h, *p_w12, *p_w2h, *p_w22;
    h16 *p_qh, *p_q2, *p_kh, *p_k2, *p_vth, *p_ath, *p_xh, *p_x2, *p_hh, *p_h2;
    float *p_attnf, *p_x, *p_y;
    cudaGetSymbolAddress((void**)&p_qinh, qin_h); cudaGetSymbolAddress((void**)&p_qin2, qin_2);
    cudaGetSymbolAddress((void**)&p_kinh, kin_h); cudaGetSymbolAddress((void**)&p_kin2, kin_2);
    cudaGetSymbolAddress((void**)&p_vinh, vin_h); cudaGetSymbolAddress((void**)&p_vin2, vin_2);
    cudaGetSymbolAddress((void**)&p_wqh, wq_h);   cudaGetSymbolAddress((void**)&p_wq2, wq_2);
    cudaGetSymbolAddress((void**)&p_wkh, wk_h);   cudaGetSymbolAddress((void**)&p_wk2, wk_2);
    cudaGetSymbolAddress((void**)&p_wvh, wv_h);   cudaGetSymbolAddress((void**)&p_wv2, wv_2);
    cudaGetSymbolAddress((void**)&p_w1h, w1_h);   cudaGetSymbolAddress((void**)&p_w12, w1_2);
    cudaGetSymbolAddress((void**)&p_w2h, w2_h);   cudaGetSymbolAddress((void**)&p_w22, w2_2);
    cudaGetSymbolAddress((void**)&p_qh, q_h);     cudaGetSymbolAddress((void**)&p_q2, q_2);
    cudaGetSymbolAddress((void**)&p_kh, k_h);     cudaGetSymbolAddress((void**)&p_k2, k_2);
    cudaGetSymbolAddress((void**)&p_vth, vt_h);
    cudaGetSymbolAddress((void**)&p_ath, at_h);
    cudaGetSymbolAddress((void**)&p_xh, x_h);     cudaGetSymbolAddress((void**)&p_x2, x_2);
    cudaGetSymbolAddress((void**)&p_hh, h_h);     cudaGetSymbolAddress((void**)&p_h2, h_2);
    cudaGetSymbolAddress((void**)&p_attnf, g_attnf);
    cudaGetSymbolAddress((void**)&p_x, g_x);
    cudaGetSymbolAddress((void**)&p_y, g_y);

    #define SET_SMEM(KER) cudaFuncSetAttribute(KER, cudaFuncAttributeMaxDynamicSharedMemorySize, SMEM_TOTAL)
    SET_SMEM((hmma_gemm<0,false,true,false,false,true>));   // q
    SET_SMEM((hmma_gemm<0,false,true,false,true,true>));    // k
    SET_SMEM((hmma_gemm<0,false,true,true,true,true>));     // vt
    SET_SMEM((hmma_gemm<2,true,true,false,false,true>));    // attn
    SET_SMEM((hmma_gemm<0,true,false,false,false,false>));  // attn@V (no corr)
    SET_SMEM((hmma_gemm<1,false,true,false,false,true>));   // FFN1
    SET_SMEM((hmma_gemm<0,true,false,false,false,true>));   // FFN2

    float* outp = (float*)d_out;
    const long long outElems  = (long long)MROWS * EMB;
    const long long attnElems = (long long)NBATCH * SEQ * SEQ;
    float* attnf = ((long long)out_size >= outElems + attnElems) ? (outp + outElems) : p_attnf;

    dim3 blk(NTHR);
    dim3 blkc(256);
    const float scale = 1.0f / 32.0f;
    const size_t sQK = (size_t)SEQ * EMB;
    const size_t sAT = (size_t)SEQ * SEQ;
    const size_t sVT = (size_t)EMB * SEQ;

    // 0) input/weight conversions
    cvt_style<false><<<MROWS*EMB/1024, blkc>>>(query, embed0, p_qinh, p_qin2);
    cvt_style<false><<<MROWS*EMB/1024, blkc>>>(key_t, embed0, p_kinh, p_kin2);
    cvt_style<false><<<MROWS*EMB/1024, blkc>>>(value, embed0, p_vinh, p_vin2);
    cvt_style<true><<<EMB*EMB/1024,   blkc>>>(Wq, nullptr, p_wqh, p_wq2);
    cvt_style<true><<<EMB*EMB/1024,   blkc>>>(Wk, nullptr, p_wkh, p_wk2);
    cvt_style<true><<<EMB*EMB/1024,   blkc>>>(Wv, nullptr, p_wvh, p_wv2);
    cvt_style<true><<<FFDIM*EMB/1024, blkc>>>(W1, nullptr, p_w1h, p_w12);
    cvt_style<true><<<EMB*FFDIM/1024, blkc>>>(W2, nullptr, p_w2h, p_w22);

    // 1) QKV projections (q A-style; k B-style; vt B-style transposed, hi only)
    dim3 gQKV(EMB / 128, MROWS / 256, 1);
    hmma_gemm<0,false,true,false,false,true><<<gQKV, blk, SMEM_TOTAL>>>(
        p_qinh, p_qin2, p_wqh, p_wq2, bq, nullptr, p_qh, p_q2, EMB, EMB, 0, 0, 0, 0.f);
    hmma_gemm<0,false,true,false,true,true><<<gQKV, blk, SMEM_TOTAL>>>(
        p_kinh, p_kin2, p_wkh, p_wk2, bk, nullptr, p_kh, p_k2, EMB, EMB, 0, 0, 0, 0.f);
    hmma_gemm<0,false,true,true,true,true><<<gQKV, blk, SMEM_TOTAL>>>(
        p_vinh, p_vin2, p_wvh, p_wv2, bv, nullptr, p_vth, nullptr, EMB, SEQ, 0, 0, 0, 0.f);

    // 2) attn = sigmoid(q @ k^T * scale): fp32 output + hi plane only
    dim3 gS(SEQ / 128, SEQ / 256, NBATCH);
    hmma_gemm<2,true,true,false,false,true><<<gS, blk, SMEM_TOTAL>>>(
        p_qh, p_q2, p_kh, p_k2, nullptr, attnf, p_ath, nullptr, EMB, SEQ, sQK, sQK, sAT, scale);

    // 3) x = attn @ v — hi-only product (CORR=false)
    dim3 gAV(EMB / 128, SEQ / 256, NBATCH);
    hmma_gemm<0,true,false,false,false,false><<<gAV, blk, SMEM_TOTAL>>>(
        p_ath, p_ath, p_vth, p_vth, nullptr, p_x, nullptr, nullptr, SEQ, EMB, sAT, sVT, sQK, 0.f);

    // 4) LN1 -> A-style planes
    layernorm_kernel<1><<<MROWS, 256>>>(p_x, g1, be1, nullptr, p_xh, p_x2);

    // 5) FFN1 = relu(x @ W1^T + b1) -> A-style planes
    dim3 gF1(FFDIM / 128, MROWS / 256, 1);
    hmma_gemm<1,false,true,false,false,true><<<gF1, blk, SMEM_TOTAL>>>(
        p_xh, p_x2, p_w1h, p_w12, b1, nullptr, p_hh, p_h2, EMB, FFDIM, 0, 0, 0, 0.f);

    // 6) FFN2 = h @ W2^T + b2 -> fp32
    dim3 gF2(EMB / 128, MROWS / 256, 1);
    hmma_gemm<0,true,false,false,false,true><<<gF2, blk, SMEM_TOTAL>>>(
        p_hh, p_h2, p_w2h, p_w22, b2, p_y, nullptr, nullptr, FFDIM, EMB, 0, 0, 0, 0.f);

    // 7) LN2 -> out
    layernorm_kernel<0><<<MROWS, 256>>>(p_y, g2, be2, outp, nullptr, nullptr);
}

// round 13
// speedup vs baseline: 1.7523x; 1.0966x over previous
#include <cuda_runtime.h>
#include <cuda_fp16.h>
#include <cstdint>
#include <math.h>

#define NBATCH 2
#define SEQ    4096
#define EMB    1024
#define FFDIM  4096
#define MROWS  (NBATCH*SEQ)   // 8192

#define SVAL 0.00390625f      // s = 2^-8
#define SINV 256.0f           // 1/s

typedef __half h16;

// ---------------- scratch (device globals; allocation-free) ----------------
__device__ h16 qin_h[MROWS*EMB], qin_2[MROWS*EMB];      // A-style
__device__ h16 kin_h[MROWS*EMB], kin_2[MROWS*EMB];      // A-style
__device__ h16 vin_h[MROWS*EMB], vin_2[MROWS*EMB];      // A-style
__device__ h16 wq_h[EMB*EMB],   wq_2[EMB*EMB];          // B-style
__device__ h16 wk_h[EMB*EMB],   wk_2[EMB*EMB];          // B-style
__device__ h16 wv_h[EMB*EMB],   wv_2[EMB*EMB];          // B-style
__device__ h16 w1_h[FFDIM*EMB];                         // hi only (FFN1 no corr)
__device__ h16 w2_h[EMB*FFDIM], w2_2[EMB*FFDIM];        // B-style
__device__ h16 q_h[MROWS*EMB],  q_2[MROWS*EMB];         // A-style
__device__ h16 k_h[MROWS*EMB],  k_2[MROWS*EMB];         // B-style
__device__ h16 vt_h[NBATCH*EMB*SEQ];                    // B-side hi (no corr consumer)
__device__ h16 at_h[(size_t)NBATCH*SEQ*SEQ];            // A-side hi (no corr consumer)
__device__ h16 x_h[MROWS*EMB];                          // A-side hi (FFN1 no corr)
__device__ h16 h_h[MROWS*FFDIM], h_2[MROWS*FFDIM];      // A-style (FFN2 corr lives)
__device__ float g_attnf[(size_t)NBATCH*SEQ*SEQ];
__device__ float g_x[MROWS*EMB];
__device__ float g_y[MROWS*EMB];

// ---------------- helpers ----------------
__device__ __forceinline__ uint32_t smem_u32(const void* p) {
    uint32_t a;
    asm("{ .reg .u64 t; cvta.to.shared.u64 t, %1; cvt.u32.u64 %0, t; }" : "=r"(a) : "l"(p));
    return a;
}
__device__ __forceinline__ void ldsm4(uint32_t r[4], uint32_t addr) {
    asm volatile("ldmatrix.sync.aligned.m8n8.x4.shared.b16 {%0,%1,%2,%3}, [%4];"
                 : "=r"(r[0]), "=r"(r[1]), "=r"(r[2]), "=r"(r[3]) : "r"(addr));
}
__device__ __forceinline__ void mma_f32(float c[4], const uint32_t a[4],
                                        uint32_t b0, uint32_t b1) {
    asm volatile("mma.sync.aligned.m16n8k16.row.col.f32.f16.f16.f32 "
                 "{%0,%1,%2,%3}, {%4,%5,%6,%7}, {%8,%9}, {%0,%1,%2,%3};"
                 : "+f"(c[0]), "+f"(c[1]), "+f"(c[2]), "+f"(c[3])
                 : "r"(a[0]), "r"(a[1]), "r"(a[2]), "r"(a[3]), "r"(b0), "r"(b1));
}
__device__ __forceinline__ void mma_f16(uint32_t c[2], const uint32_t a[4],
                                        uint32_t b0, uint32_t b1) {
    asm volatile("mma.sync.aligned.m16n8k16.row.col.f16.f16.f16.f16 "
                 "{%0,%1}, {%2,%3,%4,%5}, {%6,%7}, {%0,%1};"
                 : "+r"(c[0]), "+r"(c[1])
                 : "r"(a[0]), "r"(a[1]), "r"(a[2]), "r"(a[3]), "r"(b0), "r"(b1));
}
__device__ __forceinline__ void cpasync16(uint32_t dst, const void* src) {
    asm volatile("cp.async.cg.shared.global [%0], [%1], 16;" :: "r"(dst), "l"(src) : "memory");
}
#define CP_COMMIT() asm volatile("cp.async.commit_group;" ::: "memory")
#define CP_WAIT(n)  asm volatile("cp.async.wait_group %0;" :: "n"(n) : "memory")

// fp32 -> (hi, style-combined second plane)
template<bool BSTYLE>
__device__ __forceinline__ void style1(float x, h16& H, h16& P) {
    const __half h = __float2half_rn(x);
    const float hf = __half2float(h);
    const float lf = x - hf;
    H = h;
    P = BSTYLE ? __float2half_rn(hf + lf * SINV)
               : __float2half_rn(lf + hf * SVAL);
}
template<bool BSTYLE>
__device__ __forceinline__ void style4(const float4& f, uint2& H, uint2& P) {
    __half2 h01, h23, p01, p23;
    style1<BSTYLE>(f.x, h01.x, p01.x);
    style1<BSTYLE>(f.y, h01.y, p01.y);
    style1<BSTYLE>(f.z, h23.x, p23.x);
    style1<BSTYLE>(f.w, h23.y, p23.y);
    H.x = *reinterpret_cast<uint32_t*>(&h01);
    H.y = *reinterpret_cast<uint32_t*>(&h23);
    P.x = *reinterpret_cast<uint32_t*>(&p01);
    P.y = *reinterpret_cast<uint32_t*>(&p23);
}

// ---------------- elementwise converter ----------------
template<bool BSTYLE>
__global__ void __launch_bounds__(256)
cvt_style(const float* __restrict__ a, const float* __restrict__ b,
          h16* __restrict__ hi, h16* __restrict__ p2)
{
    const size_t i4 = ((size_t)blockIdx.x * 256 + threadIdx.x) * 4;
    float4 f = *(const float4*)(a + i4);
    if (b) {
        const float4 e = *(const float4*)(b + i4);
        f.x += e.x; f.y += e.y; f.z += e.z; f.w += e.w;
    }
    uint2 H, P;
    style4<BSTYLE>(f, H, P);
    *(uint2*)(hi + i4) = H;
    if (p2) *(uint2*)(p2 + i4) = P;
}

// ---------------- HMMA GEMM: C[M,N] = op( A[M,K] @ B[N,K]^T ) -----------------
// CTA tile 256x128, 512 threads, 16 warps 4x4, warp tile 64x32. K-chunk 64.
// CORR=true: D1 = Ah*Bh (f32 acc), P = A2*B2 (f16 acc), C = (1-s)*D1 + P.
// CORR=false: C = Ah*Bh (hi-only, half the MMA work).
// Stage 96KB: Ah(32K) | A2(32K) | Bh(16K) | B2(16K), SW128. NS=2 cp.async.
#define NS 2
#define A_PLANE 32768
#define B_PLANE 16384
#define STAGE_BYTES 98304
#define EPI_PITCH   132
#define EPI_PITCH_T 260
#define SMEM_TOTAL  (NS*STAGE_BYTES)    // 196608
#define NTHR 512

template<int OP, bool OUTF, bool OUTB, bool TRANS, bool OSTYLE, bool CORR>
__global__ void __launch_bounds__(NTHR)
hmma_gemm(const h16* __restrict__ Ahi, const h16* __restrict__ A2,
          const h16* __restrict__ Bhi, const h16* __restrict__ B2,
          const float* __restrict__ bias,
          float* __restrict__ Cf, h16* __restrict__ Chi, h16* __restrict__ C2,
          int K, int ldC, size_t sA, size_t sB, size_t sC, float scale)
{
    extern __shared__ char smem[];
    const uint32_t sbase = smem_u32(smem);

    const int t = threadIdx.x;
    const int w = t >> 5, lane = t & 31;
    const int wm = w >> 2, wn = w & 3;            // warp grid 4 x 4

    const int bz = blockIdx.z;
    Ahi += (size_t)bz * sA;  A2 += (size_t)bz * sA;
    Bhi += (size_t)bz * sB;  B2 += (size_t)bz * sB;
    const int mBase = blockIdx.y * 256;
    const int nBase = blockIdx.x * 128;

    float    accF[4][4][4];
    uint32_t accP[4][4][2];
    #pragma unroll
    for (int mi = 0; mi < 4; mi++)
        #pragma unroll
        for (int nj = 0; nj < 4; nj++) {
            #pragma unroll
            for (int e = 0; e < 4; e++) accF[mi][nj][e] = 0.f;
            accP[mi][nj][0] = 0u; accP[mi][nj][1] = 0u;
        }

    const int nk = K >> 6;

    // cp.async mapping
    const int arow = t >> 1;
    const uint32_t arx = ((uint32_t)(arow & 7)) << 4;
    const uint32_t arowoff = (uint32_t)arow * 128;
    const int brow = t >> 2;
    const uint32_t brx = ((uint32_t)(brow & 7)) << 4;
    const uint32_t browoff = (uint32_t)brow * 128;
    const size_t gArow = (size_t)(mBase + arow) * K;
    const size_t gBrow = (size_t)(nBase + brow) * K;

    auto ISSUE = [&](int kc, int s) {
        const int kb = kc << 6;
        const uint32_t st = sbase + (uint32_t)s * STAGE_BYTES;
        #pragma unroll
        for (int c = 0; c < 4; c++) {
            const int col16 = (t & 1) * 4 + c;
            const uint32_t d = arowoff + (((uint32_t)col16 * 16) ^ arx);
            const int kk = kb + col16 * 8;
            cpasync16(st + d, Ahi + gArow + kk);
            if (CORR) cpasync16(st + A_PLANE + d, A2 + gArow + kk);
        }
        #pragma unroll
        for (int c = 0; c < 2; c++) {
            const int col16 = (t & 3) * 2 + c;
            const uint32_t d = browoff + (((uint32_t)col16 * 16) ^ brx);
            const int kk = kb + col16 * 8;
            cpasync16(st + 2*A_PLANE + d, Bhi + gBrow + kk);
            if (CORR) cpasync16(st + 2*A_PLANE + B_PLANE + d, B2 + gBrow + kk);
        }
    };

    // ldmatrix addressing
    const uint32_t arow128 = (uint32_t)(wm * 64 + (lane & 15)) * 128;
    const uint32_t a16     = ((uint32_t)(lane >> 4)) << 4;
    const uint32_t axor    = ((uint32_t)(lane & 7)) << 4;
    const uint32_t brow128 = (uint32_t)(wn * 32 + ((lane >> 4) << 3) + (lane & 7)) * 128;
    const uint32_t b16     = ((uint32_t)((lane >> 3) & 1)) << 4;

    auto COMPUTE = [&](int s) {
        const uint32_t st = sbase + (uint32_t)s * STAGE_BYTES;
        #pragma unroll
        for (int ki = 0; ki < 4; ki++) {
            const uint32_t kba = (uint32_t)(ki * 32);
            // pass 1: main product (f32 acc)
            {
                uint32_t Af[4][4], Bf[4][2];
                #pragma unroll
                for (int mi = 0; mi < 4; mi++)
                    ldsm4(Af[mi], st + arow128 + mi * 2048 + ((kba + a16) ^ axor));
                #pragma unroll
                for (int nx = 0; nx < 2; nx++) {
                    uint32_t tb[4];
                    ldsm4(tb, st + 2*A_PLANE + brow128 + nx * 2048 + ((kba + b16) ^ axor));
                    Bf[nx*2][0]   = tb[0]; Bf[nx*2][1]   = tb[1];
                    Bf[nx*2+1][0] = tb[2]; Bf[nx*2+1][1] = tb[3];
                }
                #pragma unroll
                for (int nj = 0; nj < 4; nj++)
                    #pragma unroll
                    for (int mi = 0; mi < 4; mi++)
                        mma_f32(accF[mi][nj], Af[mi], Bf[nj][0], Bf[nj][1]);
            }
            // pass 2: folded correction product (f16 acc)
            if (CORR) {
                uint32_t Af[4][4], Bf[4][2];
                #pragma unroll
                for (int mi = 0; mi < 4; mi++)
                    ldsm4(Af[mi], st + A_PLANE + arow128 + mi * 2048 + ((kba + a16) ^ axor));
                #pragma unroll
                for (int nx = 0; nx < 2; nx++) {
                    uint32_t tb[4];
                    ldsm4(tb, st + 2*A_PLANE + B_PLANE + brow128 + nx * 2048 + ((kba + b16) ^ axor));
                    Bf[nx*2][0]   = tb[0]; Bf[nx*2][1]   = tb[1];
                    Bf[nx*2+1][0] = tb[2]; Bf[nx*2+1][1] = tb[3];
                }
                #pragma unroll
                for (int nj = 0; nj < 4; nj++)
                    #pragma unroll
                    for (int mi = 0; mi < 4; mi++)
                        mma_f16(accP[mi][nj], Af[mi], Bf[nj][0], Bf[nj][1]);
            }
        }
    };

    // NS=2 pipeline
    ISSUE(0, 0);
    CP_COMMIT();
    for (int kc = 0; kc < nk; kc++) {
        CP_WAIT(0);
        __syncthreads();
        if (kc + 1 < nk) { ISSUE(kc + 1, (kc + 1) & 1); CP_COMMIT(); }
        COMPUTE(kc & 1);
    }
    __syncthreads();

    // ---- epilogue
    float* epi = (float*)smem;
    const int g  = lane >> 2;
    const int tq = lane & 3;
    #pragma unroll
    for (int mi = 0; mi < 4; mi++) {
        #pragma unroll
        for (int nj = 0; nj < 4; nj++) {
            const int col = wn * 32 + nj * 8 + tq * 2;
            const __half2 c01 = *reinterpret_cast<const __half2*>(&accP[mi][nj][0]);
            const __half2 c23 = *reinterpret_cast<const __half2*>(&accP[mi][nj][1]);
            #pragma unroll
            for (int half = 0; half < 2; half++) {
                const int m = wm * 64 + mi * 16 + g + half * 8;
                const float d0 = accF[mi][nj][half*2 + 0];
                const float d1 = accF[mi][nj][half*2 + 1];
                float v0, v1;
                if (CORR) {
                    v0 = fmaf(-SVAL, d0, d0) + (half ? __half2float(c23.x) : __half2float(c01.x));
                    v1 = fmaf(-SVAL, d1, d1) + (half ? __half2float(c23.y) : __half2float(c01.y));
                } else {
                    v0 = d0; v1 = d1;
                }
                if (OP == 2) {
                    v0 = 1.f / (1.f + __expf(-v0 * scale));
                    v1 = 1.f / (1.f + __expf(-v1 * scale));
                } else {
                    if (bias) { v0 += bias[nBase + col]; v1 += bias[nBase + col + 1]; }
                    if (OP == 1) { v0 = fmaxf(v0, 0.f); v1 = fmaxf(v1, 0.f); }
                }
                if (TRANS) {
                    epi[(col)     * EPI_PITCH_T + m] = v0;
                    epi[(col + 1) * EPI_PITCH_T + m] = v1;
                } else {
                    epi[m * EPI_PITCH + col]     = v0;
                    epi[m * EPI_PITCH + col + 1] = v1;
                }
            }
        }
    }
    __syncthreads();

    if (TRANS) {
        const int r  = t >> 2;            // 0..127
        const int ch = (t & 3) * 64;      // 0..192
        const size_t boffs = (size_t)(mBase >> 12) * ((size_t)EMB * SEQ);
        const size_t rowOff = boffs + (size_t)(nBase + r) * SEQ + (size_t)(mBase & (SEQ - 1)) + ch;
        #pragma unroll
        for (int i = 0; i < 16; i++) {
            const float* e = &epi[r * EPI_PITCH_T + ch + i * 4];
            const float4 f = make_float4(e[0], e[1], e[2], e[3]);
            if (OUTF) *(float4*)(Cf + rowOff + i * 4) = f;
            if (OUTB) {
                uint2 H, P;
                style4<OSTYLE>(f, H, P);
                *(uint2*)(Chi + rowOff + i * 4) = H;
                if (C2) *(uint2*)(C2 + rowOff + i * 4) = P;
            }
        }
    } else {
        const int r  = t >> 1;            // 0..255
        const int ch = (t & 1) * 64;
        const size_t rowOff = (size_t)bz * sC + (size_t)(mBase + r) * ldC + nBase + ch;
        #pragma unroll
        for (int i = 0; i < 16; i++) {
            const float* e = &epi[r * EPI_PITCH + ch + i * 4];
            const float4 f = make_float4(e[0], e[1], e[2], e[3]);
            if (OUTF) *(float4*)(Cf + rowOff + i * 4) = f;
            if (OUTB) {
                uint2 H, P;
                style4<OSTYLE>(f, H, P);
                *(uint2*)(Chi + rowOff + i * 4) = H;
                if (C2) *(uint2*)(C2 + rowOff + i * 4) = P;
            }
        }
    }
}

// ---------------- LayerNorm ----------------
// BF=0: write fp32; BF=1: write fp16 planes (hi, optional A-style second)
template<int BF>
__global__ void __launch_bounds__(256)
layernorm_kernel(const float* __restrict__ x, const float* __restrict__ g,
                 const float* __restrict__ b, float* __restrict__ outf,
                 h16* __restrict__ ohi, h16* __restrict__ o2)
{
    const int row = blockIdx.x;
    const float* xr = x + (size_t)row * EMB;
    const int t = threadIdx.x;

    const float4 v = *(const float4*)(xr + t * 4);
    float s  = v.x + v.y + v.z + v.w;
    float ss = v.x * v.x + v.y * v.y + v.z * v.z + v.w * v.w;

    __shared__ float shs[8], shss[8], shmu[1], shinv[1];
    const int lane = t & 31, w = t >> 5;
    #pragma unroll
    for (int o = 16; o > 0; o >>= 1) {
        s  += __shfl_down_sync(0xffffffffu, s,  o);
        ss += __shfl_down_sync(0xffffffffu, ss, o);
    }
    if (lane == 0) { shs[w] = s; shss[w] = ss; }
    __syncthreads();
    if (w == 0) {
        float s2  = (lane < 8) ? shs[lane]  : 0.f;
        float ss2 = (lane < 8) ? shss[lane] : 0.f;
        #pragma unroll
        for (int o = 4; o > 0; o >>= 1) {
            s2  += __shfl_down_sync(0xffffffffu, s2,  o);
            ss2 += __shfl_down_sync(0xffffffffu, ss2, o);
        }
        if (lane == 0) {
            const float mu  = s2 * (1.f / EMB);
            const float var = ss2 * (1.f / EMB) - mu * mu;
            shmu[0]  = mu;
            shinv[0] = rsqrtf(var + 1e-5f);
        }
    }
    __syncthreads();
    const float mu = shmu[0], inv = shinv[0];

    const float4 gv = *(const float4*)(g + t * 4);
    const float4 bv = *(const float4*)(b + t * 4);
    float4 o;
    o.x = (v.x - mu) * inv * gv.x + bv.x;
    o.y = (v.y - mu) * inv * gv.y + bv.y;
    o.z = (v.z - mu) * inv * gv.z + bv.z;
    o.w = (v.w - mu) * inv * gv.w + bv.w;
    const size_t off = (size_t)row * EMB + t * 4;
    if (BF == 0) {
        *(float4*)(outf + off) = o;
    } else {
        uint2 H, P;
        style4<false>(o, H, P);
        *(uint2*)(ohi + off) = H;
        if (o2) *(uint2*)(o2 + off) = P;
    }
}

// ---------------- launch ----------------
extern "C" void kernel_launch(void* const* d_in, const int* in_sizes, int n_in,
                              void* d_out, int out_size)
{
    const float* value  = (const float*)d_in[0];
    const float* key_t  = (const float*)d_in[1];
    const float* query  = (const float*)d_in[2];
    const float* embed0 = (const float*)d_in[3];
    const float* Wq = (const float*)d_in[4];
    const float* bq = (const float*)d_in[5];
    const float* Wk = (const float*)d_in[6];
    const float* bk = (const float*)d_in[7];
    const float* Wv = (const float*)d_in[8];
    const float* bv = (const float*)d_in[9];
    const float* W1 = (const float*)d_in[10];
    const float* b1 = (const float*)d_in[11];
    const float* W2 = (const float*)d_in[12];
    const float* b2 = (const float*)d_in[13];
    const float* g1  = (const float*)d_in[14];
    const float* be1 = (const float*)d_in[15];
    const float* g2  = (const float*)d_in[16];
    const float* be2 = (const float*)d_in[17];

    h16 *p_qinh, *p_qin2, *p_kinh, *p_kin2, *p_vinh, *p_vin2;
    h16 *p_wqh, *p_wq2, *p_wkh, *p_wk2, *p_wvh, *p_wv2, *p_w1h, *p_w2h, *p_w22;
    h16 *p_qh, *p_q2, *p_kh, *p_k2, *p_vth, *p_ath, *p_xh, *p_hh, *p_h2;
    float *p_attnf, *p_x, *p_y;
    cudaGetSymbolAddress((void**)&p_qinh, qin_h); cudaGetSymbolAddress((void**)&p_qin2, qin_2);
    cudaGetSymbolAddress((void**)&p_kinh, kin_h); cudaGetSymbolAddress((void**)&p_kin2, kin_2);
    cudaGetSymbolAddress((void**)&p_vinh, vin_h); cudaGetSymbolAddress((void**)&p_vin2, vin_2);
    cudaGetSymbolAddress((void**)&p_wqh, wq_h);   cudaGetSymbolAddress((void**)&p_wq2, wq_2);
    cudaGetSymbolAddress((void**)&p_wkh, wk_h);   cudaGetSymbolAddress((void**)&p_wk2, wk_2);
    cudaGetSymbolAddress((void**)&p_wvh, wv_h);   cudaGetSymbolAddress((void**)&p_wv2, wv_2);
    cudaGetSymbolAddress((void**)&p_w1h, w1_h);
    cudaGetSymbolAddress((void**)&p_w2h, w2_h);   cudaGetSymbolAddress((void**)&p_w22, w2_2);
    cudaGetSymbolAddress((void**)&p_qh, q_h);     cudaGetSymbolAddress((void**)&p_q2, q_2);
    cudaGetSymbolAddress((void**)&p_kh, k_h);     cudaGetSymbolAddress((void**)&p_k2, k_2);
    cudaGetSymbolAddress((void**)&p_vth, vt_h);
    cudaGetSymbolAddress((void**)&p_ath, at_h);
    cudaGetSymbolAddress((void**)&p_xh, x_h);
    cudaGetSymbolAddress((void**)&p_hh, h_h);     cudaGetSymbolAddress((void**)&p_h2, h_2);
    cudaGetSymbolAddress((void**)&p_attnf, g_attnf);
    cudaGetSymbolAddress((void**)&p_x, g_x);
    cudaGetSymbolAddress((void**)&p_y, g_y);

    #define SET_SMEM(KER) cudaFuncSetAttribute(KER, cudaFuncAttributeMaxDynamicSharedMemorySize, SMEM_TOTAL)
    SET_SMEM((hmma_gemm<0,false,true,false,false,true>));   // q
    SET_SMEM((hmma_gemm<0,false,true,false,true,true>));    // k
    SET_SMEM((hmma_gemm<0,false,true,true,true,true>));     // vt
    SET_SMEM((hmma_gemm<2,true,true,false,false,true>));    // attn
    SET_SMEM((hmma_gemm<0,true,false,false,false,false>));  // attn@V (no corr)
    SET_SMEM((hmma_gemm<1,false,true,false,false,false>));  // FFN1 (no corr, A-style out)
    SET_SMEM((hmma_gemm<0,true,false,false,false,true>));   // FFN2

    float* outp = (float*)d_out;
    const long long outElems  = (long long)MROWS * EMB;
    const long long attnElems = (long long)NBATCH * SEQ * SEQ;
    float* attnf = ((long long)out_size >= outElems + attnElems) ? (outp + outElems) : p_attnf;

    dim3 blk(NTHR);
    dim3 blkc(256);
    const float scale = 1.0f / 32.0f;
    const size_t sQK = (size_t)SEQ * EMB;
    const size_t sAT = (size_t)SEQ * SEQ;
    const size_t sVT = (size_t)EMB * SEQ;

    // 0) input/weight conversions
    cvt_style<false><<<MROWS*EMB/1024, blkc>>>(query, embed0, p_qinh, p_qin2);
    cvt_style<false><<<MROWS*EMB/1024, blkc>>>(key_t, embed0, p_kinh, p_kin2);
    cvt_style<false><<<MROWS*EMB/1024, blkc>>>(value, embed0, p_vinh, p_vin2);
    cvt_style<true><<<EMB*EMB/1024,   blkc>>>(Wq, nullptr, p_wqh, p_wq2);
    cvt_style<true><<<EMB*EMB/1024,   blkc>>>(Wk, nullptr, p_wkh, p_wk2);
    cvt_style<true><<<EMB*EMB/1024,   blkc>>>(Wv, nullptr, p_wvh, p_wv2);
    cvt_style<true><<<FFDIM*EMB/1024, blkc>>>(W1, nullptr, p_w1h, nullptr);
    cvt_style<true><<<EMB*FFDIM/1024, blkc>>>(W2, nullptr, p_w2h, p_w22);

    // 1) QKV projections (q A-style; k B-style; vt B-style transposed, hi only)
    dim3 gQKV(EMB / 128, MROWS / 256, 1);
    hmma_gemm<0,false,true,false,false,true><<<gQKV, blk, SMEM_TOTAL>>>(
        p_qinh, p_qin2, p_wqh, p_wq2, bq, nullptr, p_qh, p_q2, EMB, EMB, 0, 0, 0, 0.f);
    hmma_gemm<0,false,true,false,true,true><<<gQKV, blk, SMEM_TOTAL>>>(
        p_kinh, p_kin2, p_wkh, p_wk2, bk, nullptr, p_kh, p_k2, EMB, EMB, 0, 0, 0, 0.f);
    hmma_gemm<0,false,true,true,true,true><<<gQKV, blk, SMEM_TOTAL>>>(
        p_vinh, p_vin2, p_wvh, p_wv2, bv, nullptr, p_vth, nullptr, EMB, SEQ, 0, 0, 0, 0.f);

    // 2) attn = sigmoid(q @ k^T * scale): fp32 output + hi plane only
    dim3 gS(SEQ / 128, SEQ / 256, NBATCH);
    hmma_gemm<2,true,true,false,false,true><<<gS, blk, SMEM_TOTAL>>>(
        p_qh, p_q2, p_kh, p_k2, nullptr, attnf, p_ath, nullptr, EMB, SEQ, sQK, sQK, sAT, scale);

    // 3) x = attn @ v — hi-only product (CORR=false)
    dim3 gAV(EMB / 128, SEQ / 256, NBATCH);
    hmma_gemm<0,true,false,false,false,false><<<gAV, blk, SMEM_TOTAL>>>(
        p_ath, p_ath, p_vth, p_vth, nullptr, p_x, nullptr, nullptr, SEQ, EMB, sAT, sVT, sQK, 0.f);

    // 4) LN1 -> hi plane only (FFN1 is hi-only)
    layernorm_kernel<1><<<MROWS, 256>>>(p_x, g1, be1, nullptr, p_xh, nullptr);

    // 5) FFN1 = relu(x @ W1^T + b1) — hi-only product, but emit A-style planes for FFN2
    dim3 gF1(FFDIM / 128, MROWS / 256, 1);
    hmma_gemm<1,false,true,false,false,false><<<gF1, blk, SMEM_TOTAL>>>(
        p_xh, p_xh, p_w1h, p_w1h, b1, nullptr, p_hh, p_h2, EMB, FFDIM, 0, 0, 0, 0.f);

    // 6) FFN2 = h @ W2^T + b2 -> fp32 (corrected)
    dim3 gF2(EMB / 128, MROWS / 256, 1);
    hmma_gemm<0,true,false,false,false,true><<<gF2, blk, SMEM_TOTAL>>>(
        p_hh, p_h2, p_w2h, p_w22, b2, p_y, nullptr, nullptr, FFDIM, EMB, 0, 0, 0, 0.f);

    // 7) LN2 -> out
    layernorm_kernel<0><<<MROWS, 256>>>(p_y, g2, be2, outp, nullptr, nullptr);
}

// round 14
// speedup vs baseline: 2.0674x; 1.1798x over previous
#include <cuda_runtime.h>
#include <cuda_fp16.h>
#include <cstdint>
#include <math.h>

#define NBATCH 2
#define SEQ    4096
#define EMB    1024
#define FFDIM  4096
#define MROWS  (NBATCH*SEQ)   // 8192

#define SVAL 0.00390625f      // s = 2^-8
#define SINV 256.0f           // 1/s

typedef __half h16;

// ---------------- scratch (device globals; allocation-free) ----------------
__device__ h16 qin_h[MROWS*EMB], qin_2[MROWS*EMB];      // A-style
__device__ h16 kin_h[MROWS*EMB], kin_2[MROWS*EMB];      // A-style
__device__ h16 vin_h[MROWS*EMB], vin_2[MROWS*EMB];      // A-style
__device__ h16 wq_h[EMB*EMB],   wq_2[EMB*EMB];          // B-style
__device__ h16 wk_h[EMB*EMB],   wk_2[EMB*EMB];          // B-style
__device__ h16 wv_h[EMB*EMB],   wv_2[EMB*EMB];          // B-style
__device__ h16 w1_h[FFDIM*EMB];                         // hi only (FFN1 no corr)
__device__ h16 w2_h[EMB*FFDIM];                         // hi only (FFN2 no corr)
__device__ h16 q_h[MROWS*EMB],  q_2[MROWS*EMB];         // A-style
__device__ h16 k_h[MROWS*EMB],  k_2[MROWS*EMB];         // B-style
__device__ h16 vt_h[NBATCH*EMB*SEQ];                    // B-side hi (no corr consumer)
__device__ h16 at_h[(size_t)NBATCH*SEQ*SEQ];            // A-side hi (no corr consumer)
__device__ h16 x_h[MROWS*EMB];                          // A-side hi (FFN1 no corr)
__device__ h16 h_h[MROWS*FFDIM];                        // hi only (FFN2 no corr)
__device__ float g_attnf[(size_t)NBATCH*SEQ*SEQ];
__device__ float g_x[MROWS*EMB];
__device__ float g_y[MROWS*EMB];

// ---------------- helpers ----------------
__device__ __forceinline__ uint32_t smem_u32(const void* p) {
    uint32_t a;
    asm("{ .reg .u64 t; cvta.to.shared.u64 t, %1; cvt.u32.u64 %0, t; }" : "=r"(a) : "l"(p));
    return a;
}
__device__ __forceinline__ void ldsm4(uint32_t r[4], uint32_t addr) {
    asm volatile("ldmatrix.sync.aligned.m8n8.x4.shared.b16 {%0,%1,%2,%3}, [%4];"
                 : "=r"(r[0]), "=r"(r[1]), "=r"(r[2]), "=r"(r[3]) : "r"(addr));
}
__device__ __forceinline__ void mma_f32(float c[4], const uint32_t a[4],
                                        uint32_t b0, uint32_t b1) {
    asm volatile("mma.sync.aligned.m16n8k16.row.col.f32.f16.f16.f32 "
                 "{%0,%1,%2,%3}, {%4,%5,%6,%7}, {%8,%9}, {%0,%1,%2,%3};"
                 : "+f"(c[0]), "+f"(c[1]), "+f"(c[2]), "+f"(c[3])
                 : "r"(a[0]), "r"(a[1]), "r"(a[2]), "r"(a[3]), "r"(b0), "r"(b1));
}
__device__ __forceinline__ void mma_f16(uint32_t c[2], const uint32_t a[4],
                                        uint32_t b0, uint32_t b1) {
    asm volatile("mma.sync.aligned.m16n8k16.row.col.f16.f16.f16.f16 "
                 "{%0,%1}, {%2,%3,%4,%5}, {%6,%7}, {%0,%1};"
                 : "+r"(c[0]), "+r"(c[1])
                 : "r"(a[0]), "r"(a[1]), "r"(a[2]), "r"(a[3]), "r"(b0), "r"(b1));
}
__device__ __forceinline__ void cpasync16(uint32_t dst, const void* src) {
    asm volatile("cp.async.cg.shared.global [%0], [%1], 16;" :: "r"(dst), "l"(src) : "memory");
}
#define CP_COMMIT() asm volatile("cp.async.commit_group;" ::: "memory")
#define CP_WAIT(n)  asm volatile("cp.async.wait_group %0;" :: "n"(n) : "memory")

// fp32 -> (hi, style-combined second plane)
template<bool BSTYLE>
__device__ __forceinline__ void style1(float x, h16& H, h16& P) {
    const __half h = __float2half_rn(x);
    const float hf = __half2float(h);
    const float lf = x - hf;
    H = h;
    P = BSTYLE ? __float2half_rn(hf + lf * SINV)
               : __float2half_rn(lf + hf * SVAL);
}
template<bool BSTYLE>
__device__ __forceinline__ void style4(const float4& f, uint2& H, uint2& P) {
    __half2 h01, h23, p01, p23;
    style1<BSTYLE>(f.x, h01.x, p01.x);
    style1<BSTYLE>(f.y, h01.y, p01.y);
    style1<BSTYLE>(f.z, h23.x, p23.x);
    style1<BSTYLE>(f.w, h23.y, p23.y);
    H.x = *reinterpret_cast<uint32_t*>(&h01);
    H.y = *reinterpret_cast<uint32_t*>(&h23);
    P.x = *reinterpret_cast<uint32_t*>(&p01);
    P.y = *reinterpret_cast<uint32_t*>(&p23);
}

// ---------------- elementwise converter ----------------
template<bool BSTYLE>
__global__ void __launch_bounds__(256)
cvt_style(const float* __restrict__ a, const float* __restrict__ b,
          h16* __restrict__ hi, h16* __restrict__ p2)
{
    const size_t i4 = ((size_t)blockIdx.x * 256 + threadIdx.x) * 4;
    float4 f = *(const float4*)(a + i4);
    if (b) {
        const float4 e = *(const float4*)(b + i4);
        f.x += e.x; f.y += e.y; f.z += e.z; f.w += e.w;
    }
    uint2 H, P;
    style4<BSTYLE>(f, H, P);
    *(uint2*)(hi + i4) = H;
    if (p2) *(uint2*)(p2 + i4) = P;
}

// ---------------- HMMA GEMM: C[M,N] = op( A[M,K] @ B[N,K]^T ) -----------------
// CTA tile 256x128, 512 threads, 16 warps 4x4, warp tile 64x32. K-chunk 64.
// CORR=true: D1 = Ah*Bh (f32 acc), P = A2*B2 (f16 acc), C = (1-s)*D1 + P.
// CORR=false: C = Ah*Bh (hi-only, half the MMA work).
// Stage 96KB: Ah(32K) | A2(32K) | Bh(16K) | B2(16K), SW128. NS=2 cp.async.
#define NS 2
#define A_PLANE 32768
#define B_PLANE 16384
#define STAGE_BYTES 98304
#define EPI_PITCH   132
#define EPI_PITCH_T 260
#define SMEM_TOTAL  (NS*STAGE_BYTES)    // 196608
#define NTHR 512

template<int OP, bool OUTF, bool OUTB, bool TRANS, bool OSTYLE, bool CORR>
__global__ void __launch_bounds__(NTHR)
hmma_gemm(const h16* __restrict__ Ahi, const h16* __restrict__ A2,
          const h16* __restrict__ Bhi, const h16* __restrict__ B2,
          const float* __restrict__ bias,
          float* __restrict__ Cf, h16* __restrict__ Chi, h16* __restrict__ C2,
          int K, int ldC, size_t sA, size_t sB, size_t sC, float scale)
{
    extern __shared__ char smem[];
    const uint32_t sbase = smem_u32(smem);

    const int t = threadIdx.x;
    const int w = t >> 5, lane = t & 31;
    const int wm = w >> 2, wn = w & 3;            // warp grid 4 x 4

    const int bz = blockIdx.z;
    Ahi += (size_t)bz * sA;  A2 += (size_t)bz * sA;
    Bhi += (size_t)bz * sB;  B2 += (size_t)bz * sB;
    const int mBase = blockIdx.y * 256;
    const int nBase = blockIdx.x * 128;

    float    accF[4][4][4];
    uint32_t accP[4][4][2];
    #pragma unroll
    for (int mi = 0; mi < 4; mi++)
        #pragma unroll
        for (int nj = 0; nj < 4; nj++) {
            #pragma unroll
            for (int e = 0; e < 4; e++) accF[mi][nj][e] = 0.f;
            accP[mi][nj][0] = 0u; accP[mi][nj][1] = 0u;
        }

    const int nk = K >> 6;

    // cp.async mapping
    const int arow = t >> 1;
    const uint32_t arx = ((uint32_t)(arow & 7)) << 4;
    const uint32_t arowoff = (uint32_t)arow * 128;
    const int brow = t >> 2;
    const uint32_t brx = ((uint32_t)(brow & 7)) << 4;
    const uint32_t browoff = (uint32_t)brow * 128;
    const size_t gArow = (size_t)(mBase + arow) * K;
    const size_t gBrow = (size_t)(nBase + brow) * K;

    auto ISSUE = [&](int kc, int s) {
        const int kb = kc << 6;
        const uint32_t st = sbase + (uint32_t)s * STAGE_BYTES;
        #pragma unroll
        for (int c = 0; c < 4; c++) {
            const int col16 = (t & 1) * 4 + c;
            const uint32_t d = arowoff + (((uint32_t)col16 * 16) ^ arx);
            const int kk = kb + col16 * 8;
            cpasync16(st + d, Ahi + gArow + kk);
            if (CORR) cpasync16(st + A_PLANE + d, A2 + gArow + kk);
        }
        #pragma unroll
        for (int c = 0; c < 2; c++) {
            const int col16 = (t & 3) * 2 + c;
            const uint32_t d = browoff + (((uint32_t)col16 * 16) ^ brx);
            const int kk = kb + col16 * 8;
            cpasync16(st + 2*A_PLANE + d, Bhi + gBrow + kk);
            if (CORR) cpasync16(st + 2*A_PLANE + B_PLANE + d, B2 + gBrow + kk);
        }
    };

    // ldmatrix addressing
    const uint32_t arow128 = (uint32_t)(wm * 64 + (lane & 15)) * 128;
    const uint32_t a16     = ((uint32_t)(lane >> 4)) << 4;
    const uint32_t axor    = ((uint32_t)(lane & 7)) << 4;
    const uint32_t brow128 = (uint32_t)(wn * 32 + ((lane >> 4) << 3) + (lane & 7)) * 128;
    const uint32_t b16     = ((uint32_t)((lane >> 3) & 1)) << 4;

    auto COMPUTE = [&](int s) {
        const uint32_t st = sbase + (uint32_t)s * STAGE_BYTES;
        #pragma unroll
        for (int ki = 0; ki < 4; ki++) {
            const uint32_t kba = (uint32_t)(ki * 32);
            // pass 1: main product (f32 acc)
            {
                uint32_t Af[4][4], Bf[4][2];
                #pragma unroll
                for (int mi = 0; mi < 4; mi++)
                    ldsm4(Af[mi], st + arow128 + mi * 2048 + ((kba + a16) ^ axor));
                #pragma unroll
                for (int nx = 0; nx < 2; nx++) {
                    uint32_t tb[4];
                    ldsm4(tb, st + 2*A_PLANE + brow128 + nx * 2048 + ((kba + b16) ^ axor));
                    Bf[nx*2][0]   = tb[0]; Bf[nx*2][1]   = tb[1];
                    Bf[nx*2+1][0] = tb[2]; Bf[nx*2+1][1] = tb[3];
                }
                #pragma unroll
                for (int nj = 0; nj < 4; nj++)
                    #pragma unroll
                    for (int mi = 0; mi < 4; mi++)
                        mma_f32(accF[mi][nj], Af[mi], Bf[nj][0], Bf[nj][1]);
            }
            // pass 2: folded correction product (f16 acc)
            if (CORR) {
                uint32_t Af[4][4], Bf[4][2];
                #pragma unroll
                for (int mi = 0; mi < 4; mi++)
                    ldsm4(Af[mi], st + A_PLANE + arow128 + mi * 2048 + ((kba + a16) ^ axor));
                #pragma unroll
                for (int nx = 0; nx < 2; nx++) {
                    uint32_t tb[4];
                    ldsm4(tb, st + 2*A_PLANE + B_PLANE + brow128 + nx * 2048 + ((kba + b16) ^ axor));
                    Bf[nx*2][0]   = tb[0]; Bf[nx*2][1]   = tb[1];
                    Bf[nx*2+1][0] = tb[2]; Bf[nx*2+1][1] = tb[3];
                }
                #pragma unroll
                for (int nj = 0; nj < 4; nj++)
                    #pragma unroll
                    for (int mi = 0; mi < 4; mi++)
                        mma_f16(accP[mi][nj], Af[mi], Bf[nj][0], Bf[nj][1]);
            }
        }
    };

    // NS=2 pipeline
    ISSUE(0, 0);
    CP_COMMIT();
    for (int kc = 0; kc < nk; kc++) {
        CP_WAIT(0);
        __syncthreads();
        if (kc + 1 < nk) { ISSUE(kc + 1, (kc + 1) & 1); CP_COMMIT(); }
        COMPUTE(kc & 1);
    }
    __syncthreads();

    // ---- epilogue
    float* epi = (float*)smem;
    const int g  = lane >> 2;
    const int tq = lane & 3;
    #pragma unroll
    for (int mi = 0; mi < 4; mi++) {
        #pragma unroll
        for (int nj = 0; nj < 4; nj++) {
            const int col = wn * 32 + nj * 8 + tq * 2;
            const __half2 c01 = *reinterpret_cast<const __half2*>(&accP[mi][nj][0]);
            const __half2 c23 = *reinterpret_cast<const __half2*>(&accP[mi][nj][1]);
            #pragma unroll
            for (int half = 0; half < 2; half++) {
                const int m = wm * 64 + mi * 16 + g + half * 8;
                const float d0 = accF[mi][nj][half*2 + 0];
                const float d1 = accF[mi][nj][half*2 + 1];
                float v0, v1;
                if (CORR) {
                    v0 = fmaf(-SVAL, d0, d0) + (half ? __half2float(c23.x) : __half2float(c01.x));
                    v1 = fmaf(-SVAL, d1, d1) + (half ? __half2float(c23.y) : __half2float(c01.y));
                } else {
                    v0 = d0; v1 = d1;
                }
                if (OP == 2) {
                    v0 = 1.f / (1.f + __expf(-v0 * scale));
                    v1 = 1.f / (1.f + __expf(-v1 * scale));
                } else {
                    if (bias) { v0 += bias[nBase + col]; v1 += bias[nBase + col + 1]; }
                    if (OP == 1) { v0 = fmaxf(v0, 0.f); v1 = fmaxf(v1, 0.f); }
                }
                if (TRANS) {
                    epi[(col)     * EPI_PITCH_T + m] = v0;
                    epi[(col + 1) * EPI_PITCH_T + m] = v1;
                } else {
                    epi[m * EPI_PITCH + col]     = v0;
                    epi[m * EPI_PITCH + col + 1] = v1;
                }
            }
        }
    }
    __syncthreads();

    if (TRANS) {
        const int r  = t >> 2;            // 0..127
        const int ch = (t & 3) * 64;      // 0..192
        const size_t boffs = (size_t)(mBase >> 12) * ((size_t)EMB * SEQ);
        const size_t rowOff = boffs + (size_t)(nBase + r) * SEQ + (size_t)(mBase & (SEQ - 1)) + ch;
        #pragma unroll
        for (int i = 0; i < 16; i++) {
            const float* e = &epi[r * EPI_PITCH_T + ch + i * 4];
            const float4 f = make_float4(e[0], e[1], e[2], e[3]);
            if (OUTF) *(float4*)(Cf + rowOff + i * 4) = f;
            if (OUTB) {
                uint2 H, P;
                style4<OSTYLE>(f, H, P);
                *(uint2*)(Chi + rowOff + i * 4) = H;
                if (C2) *(uint2*)(C2 + rowOff + i * 4) = P;
            }
        }
    } else {
        const int r  = t >> 1;            // 0..255
        const int ch = (t & 1) * 64;
        const size_t rowOff = (size_t)bz * sC + (size_t)(mBase + r) * ldC + nBase + ch;
        #pragma unroll
        for (int i = 0; i < 16; i++) {
            const float* e = &epi[r * EPI_PITCH + ch + i * 4];
            const float4 f = make_float4(e[0], e[1], e[2], e[3]);
            if (OUTF) *(float4*)(Cf + rowOff + i * 4) = f;
            if (OUTB) {
                uint2 H, P;
                style4<OSTYLE>(f, H, P);
                *(uint2*)(Chi + rowOff + i * 4) = H;
                if (C2) *(uint2*)(C2 + rowOff + i * 4) = P;
            }
        }
    }
}

// ---------------- LayerNorm ----------------
// BF=0: write fp32; BF=1: write fp16 planes (hi, optional A-style second)
template<int BF>
__global__ void __launch_bounds__(256)
layernorm_kernel(const float* __restrict__ x, const float* __restrict__ g,
                 const float* __restrict__ b, float* __restrict__ outf,
                 h16* __restrict__ ohi, h16* __restrict__ o2)
{
    const int row = blockIdx.x;
    const float* xr = x + (size_t)row * EMB;
    const int t = threadIdx.x;

    const float4 v = *(const float4*)(xr + t * 4);
    float s  = v.x + v.y + v.z + v.w;
    float ss = v.x * v.x + v.y * v.y + v.z * v.z + v.w * v.w;

    __shared__ float shs[8], shss[8], shmu[1], shinv[1];
    const int lane = t & 31, w = t >> 5;
    #pragma unroll
    for (int o = 16; o > 0; o >>= 1) {
        s  += __shfl_down_sync(0xffffffffu, s,  o);
        ss += __shfl_down_sync(0xffffffffu, ss, o);
    }
    if (lane == 0) { shs[w] = s; shss[w] = ss; }
    __syncthreads();
    if (w == 0) {
        float s2  = (lane < 8) ? shs[lane]  : 0.f;
        float ss2 = (lane < 8) ? shss[lane] : 0.f;
        #pragma unroll
        for (int o = 4; o > 0; o >>= 1) {
            s2  += __shfl_down_sync(0xffffffffu, s2,  o);
            ss2 += __shfl_down_sync(0xffffffffu, ss2, o);
        }
        if (lane == 0) {
            const float mu  = s2 * (1.f / EMB);
            const float var = ss2 * (1.f / EMB) - mu * mu;
            shmu[0]  = mu;
            shinv[0] = rsqrtf(var + 1e-5f);
        }
    }
    __syncthreads();
    const float mu = shmu[0], inv = shinv[0];

    const float4 gv = *(const float4*)(g + t * 4);
    const float4 bv = *(const float4*)(b + t * 4);
    float4 o;
    o.x = (v.x - mu) * inv * gv.x + bv.x;
    o.y = (v.y - mu) * inv * gv.y + bv.y;
    o.z = (v.z - mu) * inv * gv.z + bv.z;
    o.w = (v.w - mu) * inv * gv.w + bv.w;
    const size_t off = (size_t)row * EMB + t * 4;
    if (BF == 0) {
        *(float4*)(outf + off) = o;
    } else {
        uint2 H, P;
        style4<false>(o, H, P);
        *(uint2*)(ohi + off) = H;
        if (o2) *(uint2*)(o2 + off) = P;
    }
}

// ---------------- launch ----------------
extern "C" void kernel_launch(void* const* d_in, const int* in_sizes, int n_in,
                              void* d_out, int out_size)
{
    const float* value  = (const float*)d_in[0];
    const float* key_t  = (const float*)d_in[1];
    const float* query  = (const float*)d_in[2];
    const float* embed0 = (const float*)d_in[3];
    const float* Wq = (const float*)d_in[4];
    const float* bq = (const float*)d_in[5];
    const float* Wk = (const float*)d_in[6];
    const float* bk = (const float*)d_in[7];
    const float* Wv = (const float*)d_in[8];
    const float* bv = (const float*)d_in[9];
    const float* W1 = (const float*)d_in[10];
    const float* b1 = (const float*)d_in[11];
    const float* W2 = (const float*)d_in[12];
    const float* b2 = (const float*)d_in[13];
    const float* g1  = (const float*)d_in[14];
    const float* be1 = (const float*)d_in[15];
    const float* g2  = (const float*)d_in[16];
    const float* be2 = (const float*)d_in[17];

    h16 *p_qinh, *p_qin2, *p_kinh, *p_kin2, *p_vinh, *p_vin2;
    h16 *p_wqh, *p_wq2, *p_wkh, *p_wk2, *p_wvh, *p_wv2, *p_w1h, *p_w2h;
    h16 *p_qh, *p_q2, *p_kh, *p_k2, *p_vth, *p_ath, *p_xh, *p_hh;
    float *p_attnf, *p_x, *p_y;
    cudaGetSymbolAddress((void**)&p_qinh, qin_h); cudaGetSymbolAddress((void**)&p_qin2, qin_2);
    cudaGetSymbolAddress((void**)&p_kinh, kin_h); cudaGetSymbolAddress((void**)&p_kin2, kin_2);
    cudaGetSymbolAddress((void**)&p_vinh, vin_h); cudaGetSymbolAddress((void**)&p_vin2, vin_2);
    cudaGetSymbolAddress((void**)&p_wqh, wq_h);   cudaGetSymbolAddress((void**)&p_wq2, wq_2);
    cudaGetSymbolAddress((void**)&p_wkh, wk_h);   cudaGetSymbolAddress((void**)&p_wk2, wk_2);
    cudaGetSymbolAddress((void**)&p_wvh, wv_h);   cudaGetSymbolAddress((void**)&p_wv2, wv_2);
    cudaGetSymbolAddress((void**)&p_w1h, w1_h);
    cudaGetSymbolAddress((void**)&p_w2h, w2_h);
    cudaGetSymbolAddress((void**)&p_qh, q_h);     cudaGetSymbolAddress((void**)&p_q2, q_2);
    cudaGetSymbolAddress((void**)&p_kh, k_h);     cudaGetSymbolAddress((void**)&p_k2, k_2);
    cudaGetSymbolAddress((void**)&p_vth, vt_h);
    cudaGetSymbolAddress((void**)&p_ath, at_h);
    cudaGetSymbolAddress((void**)&p_xh, x_h);
    cudaGetSymbolAddress((void**)&p_hh, h_h);
    cudaGetSymbolAddress((void**)&p_attnf, g_attnf);
    cudaGetSymbolAddress((void**)&p_x, g_x);
    cudaGetSymbolAddress((void**)&p_y, g_y);

    #define SET_SMEM(KER) cudaFuncSetAttribute(KER, cudaFuncAttributeMaxDynamicSharedMemorySize, SMEM_TOTAL)
    SET_SMEM((hmma_gemm<0,false,true,false,false,true>));   // q
    SET_SMEM((hmma_gemm<0,false,true,false,true,true>));    // k
    SET_SMEM((hmma_gemm<0,false,true,true,true,true>));     // vt
    SET_SMEM((hmma_gemm<2,true,true,false,false,true>));    // attn
    SET_SMEM((hmma_gemm<0,true,false,false,false,false>));  // attn@V / FFN2 (no corr)
    SET_SMEM((hmma_gemm<1,false,true,false,false,false>));  // FFN1 (no corr)

    float* outp = (float*)d_out;
    const long long outElems  = (long long)MROWS * EMB;
    const long long attnElems = (long long)NBATCH * SEQ * SEQ;
    float* attnf = ((long long)out_size >= outElems + attnElems) ? (outp + outElems) : p_attnf;

    dim3 blk(NTHR);
    dim3 blkc(256);
    const float scale = 1.0f / 32.0f;
    const size_t sQK = (size_t)SEQ * EMB;
    const size_t sAT = (size_t)SEQ * SEQ;
    const size_t sVT = (size_t)EMB * SEQ;

    // 0) input/weight conversions
    cvt_style<false><<<MROWS*EMB/1024, blkc>>>(query, embed0, p_qinh, p_qin2);
    cvt_style<false><<<MROWS*EMB/1024, blkc>>>(key_t, embed0, p_kinh, p_kin2);
    cvt_style<false><<<MROWS*EMB/1024, blkc>>>(value, embed0, p_vinh, p_vin2);
    cvt_style<true><<<EMB*EMB/1024,   blkc>>>(Wq, nullptr, p_wqh, p_wq2);
    cvt_style<true><<<EMB*EMB/1024,   blkc>>>(Wk, nullptr, p_wkh, p_wk2);
    cvt_style<true><<<EMB*EMB/1024,   blkc>>>(Wv, nullptr, p_wvh, p_wv2);
    cvt_style<true><<<FFDIM*EMB/1024, blkc>>>(W1, nullptr, p_w1h, nullptr);
    cvt_style<true><<<EMB*FFDIM/1024, blkc>>>(W2, nullptr, p_w2h, nullptr);

    // 1) QKV projections (q A-style; k B-style; vt B-style transposed, hi only)
    dim3 gQKV(EMB / 128, MROWS / 256, 1);
    hmma_gemm<0,false,true,false,false,true><<<gQKV, blk, SMEM_TOTAL>>>(
        p_qinh, p_qin2, p_wqh, p_wq2, bq, nullptr, p_qh, p_q2, EMB, EMB, 0, 0, 0, 0.f);
    hmma_gemm<0,false,true,false,true,true><<<gQKV, blk, SMEM_TOTAL>>>(
        p_kinh, p_kin2, p_wkh, p_wk2, bk, nullptr, p_kh, p_k2, EMB, EMB, 0, 0, 0, 0.f);
    hmma_gemm<0,false,true,true,true,true><<<gQKV, blk, SMEM_TOTAL>>>(
        p_vinh, p_vin2, p_wvh, p_wv2, bv, nullptr, p_vth, nullptr, EMB, SEQ, 0, 0, 0, 0.f);

    // 2) attn = sigmoid(q @ k^T * scale): fp32 output + hi plane only (corrected)
    dim3 gS(SEQ / 128, SEQ / 256, NBATCH);
    hmma_gemm<2,true,true,false,false,true><<<gS, blk, SMEM_TOTAL>>>(
        p_qh, p_q2, p_kh, p_k2, nullptr, attnf, p_ath, nullptr, EMB, SEQ, sQK, sQK, sAT, scale);

    // 3) x = attn @ v — hi-only product
    dim3 gAV(EMB / 128, SEQ / 256, NBATCH);
    hmma_gemm<0,true,false,false,false,false><<<gAV, blk, SMEM_TOTAL>>>(
        p_ath, p_ath, p_vth, p_vth, nullptr, p_x, nullptr, nullptr, SEQ, EMB, sAT, sVT, sQK, 0.f);

    // 4) LN1 -> hi plane only
    layernorm_kernel<1><<<MROWS, 256>>>(p_x, g1, be1, nullptr, p_xh, nullptr);

    // 5) FFN1 = relu(x @ W1^T + b1) — hi-only product, emit hi plane only
    dim3 gF1(FFDIM / 128, MROWS / 256, 1);
    hmma_gemm<1,false,true,false,false,false><<<gF1, blk, SMEM_TOTAL>>>(
        p_xh, p_xh, p_w1h, p_w1h, b1, nullptr, p_hh, nullptr, EMB, FFDIM, 0, 0, 0, 0.f);

    // 6) FFN2 = h @ W2^T + b2 -> fp32 — hi-only product
    dim3 gF2(EMB / 128, MROWS / 256, 1);
    hmma_gemm<0,true,false,false,false,false><<<gF2, blk, SMEM_TOTAL>>>(
        p_hh, p_hh, p_w2h, p_w2h, b2, p_y, nullptr, nullptr, FFDIM, EMB, 0, 0, 0, 0.f);

    // 7) LN2 -> out
    layernorm_kernel<0><<<MROWS, 256>>>(p_y, g2, be2, outp, nullptr, nullptr);
}

// round 15
// speedup vs baseline: 2.5945x; 1.2549x over previous
#include <cuda_runtime.h>
#include <cuda_fp16.h>
#include <cstdint>
#include <math.h>

#define NBATCH 2
#define SEQ    4096
#define EMB    1024
#define FFDIM  4096
#define MROWS  (NBATCH*SEQ)   // 8192

typedef __half h16;

// ---------------- scratch (device globals; allocation-free) ----------------
__device__ h16 qin_h[MROWS*EMB];
__device__ h16 kin_h[MROWS*EMB];
__device__ h16 vin_h[MROWS*EMB];
__device__ h16 wq_h[EMB*EMB];
__device__ h16 wk_h[EMB*EMB];
__device__ h16 wv_h[EMB*EMB];
__device__ h16 w1_h[FFDIM*EMB];
__device__ h16 w2_h[EMB*FFDIM];
__device__ h16 q_h[MROWS*EMB];
__device__ h16 k_h[MROWS*EMB];
__device__ h16 vt_h[NBATCH*EMB*SEQ];
__device__ h16 at_h[(size_t)NBATCH*SEQ*SEQ];
__device__ h16 x_h[MROWS*EMB];
__device__ h16 h_h[MROWS*FFDIM];
__device__ float g_attnf[(size_t)NBATCH*SEQ*SEQ];
__device__ float g_x[MROWS*EMB];
__device__ float g_y[MROWS*EMB];

// ---------------- helpers ----------------
__device__ __forceinline__ uint32_t smem_u32(const void* p) {
    uint32_t a;
    asm("{ .reg .u64 t; cvta.to.shared.u64 t, %1; cvt.u32.u64 %0, t; }" : "=r"(a) : "l"(p));
    return a;
}
__device__ __forceinline__ void ldsm4(uint32_t r[4], uint32_t addr) {
    asm volatile("ldmatrix.sync.aligned.m8n8.x4.shared.b16 {%0,%1,%2,%3}, [%4];"
                 : "=r"(r[0]), "=r"(r[1]), "=r"(r[2]), "=r"(r[3]) : "r"(addr));
}
__device__ __forceinline__ void mma_f32(float c[4], const uint32_t a[4],
                                        uint32_t b0, uint32_t b1) {
    asm volatile("mma.sync.aligned.m16n8k16.row.col.f32.f16.f16.f32 "
                 "{%0,%1,%2,%3}, {%4,%5,%6,%7}, {%8,%9}, {%0,%1,%2,%3};"
                 : "+f"(c[0]), "+f"(c[1]), "+f"(c[2]), "+f"(c[3])
                 : "r"(a[0]), "r"(a[1]), "r"(a[2]), "r"(a[3]), "r"(b0), "r"(b1));
}
__device__ __forceinline__ void cpasync16(uint32_t dst, const void* src) {
    asm volatile("cp.async.cg.shared.global [%0], [%1], 16;" :: "r"(dst), "l"(src) : "memory");
}
#define CP_COMMIT() asm volatile("cp.async.commit_group;" ::: "memory")
#define CP_WAIT(n)  asm volatile("cp.async.wait_group %0;" :: "n"(n) : "memory")

// fp32x4 -> fp16x4 (uint2)
__device__ __forceinline__ uint2 h4cvt(const float4& f) {
    __half2 h01 = __floats2half2_rn(f.x, f.y);
    __half2 h23 = __floats2half2_rn(f.z, f.w);
    uint2 H;
    H.x = *reinterpret_cast<uint32_t*>(&h01);
    H.y = *reinterpret_cast<uint32_t*>(&h23);
    return H;
}

// ---------------- elementwise converter: hi = fp16(a [+ b]) ----------------
__global__ void __launch_bounds__(256)
cvt_h(const float* __restrict__ a, const float* __restrict__ b, h16* __restrict__ hi)
{
    const size_t i4 = ((size_t)blockIdx.x * 256 + threadIdx.x) * 4;
    float4 f = *(const float4*)(a + i4);
    if (b) {
        const float4 e = *(const float4*)(b + i4);
        f.x += e.x; f.y += e.y; f.z += e.z; f.w += e.w;
    }
    *(uint2*)(hi + i4) = h4cvt(f);
}

// ---------------- HMMA GEMM: C[M,N] = op( A[M,K] @ B[N,K]^T ) -----------------
// CTA tile 256x128, 512 threads, 16 warps 4x4, warp tile 64x32. K-chunk 64.
// Single product Ah*Bh with f32 accumulators.
// Stage 48KB: A(32K) | B(16K), SW128. NS=3 cp.async pipeline.
#define NS 3
#define A_PLANE 32768
#define STAGE_BYTES 49152
#define EPI_PITCH   132
#define EPI_PITCH_T 260
#define SMEM_TOTAL  (NS*STAGE_BYTES)    // 147456
#define NTHR 512

template<int OP, bool OUTF, bool OUTB, bool TRANS>
__global__ void __launch_bounds__(NTHR)
hmma_gemm(const h16* __restrict__ Ahi, const h16* __restrict__ Bhi,
          const float* __restrict__ bias,
          float* __restrict__ Cf, h16* __restrict__ Chi,
          int K, int ldC, size_t sA, size_t sB, size_t sC, float scale)
{
    extern __shared__ char smem[];
    const uint32_t sbase = smem_u32(smem);

    const int t = threadIdx.x;
    const int w = t >> 5, lane = t & 31;
    const int wm = w >> 2, wn = w & 3;            // warp grid 4 x 4

    const int bz = blockIdx.z;
    Ahi += (size_t)bz * sA;
    Bhi += (size_t)bz * sB;
    const int mBase = blockIdx.y * 256;
    const int nBase = blockIdx.x * 128;

    float accF[4][4][4];
    #pragma unroll
    for (int mi = 0; mi < 4; mi++)
        #pragma unroll
        for (int nj = 0; nj < 4; nj++)
            #pragma unroll
            for (int e = 0; e < 4; e++) accF[mi][nj][e] = 0.f;

    const int nk = K >> 6;

    // cp.async mapping
    const int arow = t >> 1;
    const uint32_t arx = ((uint32_t)(arow & 7)) << 4;
    const uint32_t arowoff = (uint32_t)arow * 128;
    const int brow = t >> 2;
    const uint32_t brx = ((uint32_t)(brow & 7)) << 4;
    const uint32_t browoff = (uint32_t)brow * 128;
    const size_t gArow = (size_t)(mBase + arow) * K;
    const size_t gBrow = (size_t)(nBase + brow) * K;

    auto ISSUE = [&](int kc, int s) {
        const int kb = kc << 6;
        const uint32_t st = sbase + (uint32_t)s * STAGE_BYTES;
        #pragma unroll
        for (int c = 0; c < 4; c++) {
            const int col16 = (t & 1) * 4 + c;
            const uint32_t d = arowoff + (((uint32_t)col16 * 16) ^ arx);
            cpasync16(st + d, Ahi + gArow + kb + col16 * 8);
        }
        #pragma unroll
        for (int c = 0; c < 2; c++) {
            const int col16 = (t & 3) * 2 + c;
            const uint32_t d = browoff + (((uint32_t)col16 * 16) ^ brx);
            cpasync16(st + A_PLANE + d, Bhi + gBrow + kb + col16 * 8);
        }
    };

    // ldmatrix addressing
    const uint32_t arow128 = (uint32_t)(wm * 64 + (lane & 15)) * 128;
    const uint32_t a16     = ((uint32_t)(lane >> 4)) << 4;
    const uint32_t axor    = ((uint32_t)(lane & 7)) << 4;
    const uint32_t brow128 = (uint32_t)(wn * 32 + ((lane >> 4) << 3) + (lane & 7)) * 128;
    const uint32_t b16     = ((uint32_t)((lane >> 3) & 1)) << 4;

    auto COMPUTE = [&](int s) {
        const uint32_t st = sbase + (uint32_t)s * STAGE_BYTES;
        #pragma unroll
        for (int ki = 0; ki < 4; ki++) {
            const uint32_t kba = (uint32_t)(ki * 32);
            uint32_t Af[4][4], Bf[4][2];
            #pragma unroll
            for (int mi = 0; mi < 4; mi++)
                ldsm4(Af[mi], st + arow128 + mi * 2048 + ((kba + a16) ^ axor));
            #pragma unroll
            for (int nx = 0; nx < 2; nx++) {
                uint32_t tb[4];
                ldsm4(tb, st + A_PLANE + brow128 + nx * 2048 + ((kba + b16) ^ axor));
                Bf[nx*2][0]   = tb[0]; Bf[nx*2][1]   = tb[1];
                Bf[nx*2+1][0] = tb[2]; Bf[nx*2+1][1] = tb[3];
            }
            #pragma unroll
            for (int nj = 0; nj < 4; nj++)
                #pragma unroll
                for (int mi = 0; mi < 4; mi++)
                    mma_f32(accF[mi][nj], Af[mi], Bf[nj][0], Bf[nj][1]);
        }
    };

    // NS=3 pipeline
    #pragma unroll
    for (int s = 0; s < NS - 1; s++) { ISSUE(s, s); CP_COMMIT(); }
    for (int kc = 0; kc < nk; kc++) {
        CP_WAIT(NS - 2);
        __syncthreads();
        const int kn = kc + NS - 1;
        if (kn < nk) { ISSUE(kn, kn % NS); CP_COMMIT(); }
        COMPUTE(kc % NS);
    }
    __syncthreads();

    // ---- epilogue
    float* epi = (float*)smem;
    const int g  = lane >> 2;
    const int tq = lane & 3;
    #pragma unroll
    for (int mi = 0; mi < 4; mi++) {
        #pragma unroll
        for (int nj = 0; nj < 4; nj++) {
            const int col = wn * 32 + nj * 8 + tq * 2;
            #pragma unroll
            for (int half = 0; half < 2; half++) {
                const int m = wm * 64 + mi * 16 + g + half * 8;
                float v0 = accF[mi][nj][half*2 + 0];
                float v1 = accF[mi][nj][half*2 + 1];
                if (OP == 2) {
                    v0 = 1.f / (1.f + __expf(-v0 * scale));
                    v1 = 1.f / (1.f + __expf(-v1 * scale));
                } else {
                    if (bias) { v0 += bias[nBase + col]; v1 += bias[nBase + col + 1]; }
                    if (OP == 1) { v0 = fmaxf(v0, 0.f); v1 = fmaxf(v1, 0.f); }
                }
                if (TRANS) {
                    epi[(col)     * EPI_PITCH_T + m] = v0;
                    epi[(col + 1) * EPI_PITCH_T + m] = v1;
                } else {
                    epi[m * EPI_PITCH + col]     = v0;
                    epi[m * EPI_PITCH + col + 1] = v1;
                }
            }
        }
    }
    __syncthreads();

    if (TRANS) {
        const int r  = t >> 2;            // 0..127
        const int ch = (t & 3) * 64;      // 0..192
        const size_t boffs = (size_t)(mBase >> 12) * ((size_t)EMB * SEQ);
        const size_t rowOff = boffs + (size_t)(nBase + r) * SEQ + (size_t)(mBase & (SEQ - 1)) + ch;
        #pragma unroll
        for (int i = 0; i < 16; i++) {
            const float* e = &epi[r * EPI_PITCH_T + ch + i * 4];
            const float4 f = make_float4(e[0], e[1], e[2], e[3]);
            if (OUTF) *(float4*)(Cf + rowOff + i * 4) = f;
            if (OUTB) *(uint2*)(Chi + rowOff + i * 4) = h4cvt(f);
        }
    } else {
        const int r  = t >> 1;            // 0..255
        const int ch = (t & 1) * 64;
        const size_t rowOff = (size_t)bz * sC + (size_t)(mBase + r) * ldC + nBase + ch;
        #pragma unroll
        for (int i = 0; i < 16; i++) {
            const float* e = &epi[r * EPI_PITCH + ch + i * 4];
            const float4 f = make_float4(e[0], e[1], e[2], e[3]);
            if (OUTF) *(float4*)(Cf + rowOff + i * 4) = f;
            if (OUTB) *(uint2*)(Chi + rowOff + i * 4) = h4cvt(f);
        }
    }
}

// ---------------- LayerNorm ----------------
// BF=0: write fp32; BF=1: write fp16 hi plane
template<int BF>
__global__ void __launch_bounds__(256)
layernorm_kernel(const float* __restrict__ x, const float* __restrict__ g,
                 const float* __restrict__ b, float* __restrict__ outf,
                 h16* __restrict__ ohi)
{
    const int row = blockIdx.x;
    const float* xr = x + (size_t)row * EMB;
    const int t = threadIdx.x;

    const float4 v = *(const float4*)(xr + t * 4);
    float s  = v.x + v.y + v.z + v.w;
    float ss = v.x * v.x + v.y * v.y + v.z * v.z + v.w * v.w;

    __shared__ float shs[8], shss[8], shmu[1], shinv[1];
    const int lane = t & 31, w = t >> 5;
    #pragma unroll
    for (int o = 16; o > 0; o >>= 1) {
        s  += __shfl_down_sync(0xffffffffu, s,  o);
        ss += __shfl_down_sync(0xffffffffu, ss, o);
    }
    if (lane == 0) { shs[w] = s; shss[w] = ss; }
    __syncthreads();
    if (w == 0) {
        float s2  = (lane < 8) ? shs[lane]  : 0.f;
        float ss2 = (lane < 8) ? shss[lane] : 0.f;
        #pragma unroll
        for (int o = 4; o > 0; o >>= 1) {
            s2  += __shfl_down_sync(0xffffffffu, s2,  o);
            ss2 += __shfl_down_sync(0xffffffffu, ss2, o);
        }
        if (lane == 0) {
            const float mu  = s2 * (1.f / EMB);
            const float var = ss2 * (1.f / EMB) - mu * mu;
            shmu[0]  = mu;
            shinv[0] = rsqrtf(var + 1e-5f);
        }
    }
    __syncthreads();
    const float mu = shmu[0], inv = shinv[0];

    const float4 gv = *(const float4*)(g + t * 4);
    const float4 bv = *(const float4*)(b + t * 4);
    float4 o;
    o.x = (v.x - mu) * inv * gv.x + bv.x;
    o.y = (v.y - mu) * inv * gv.y + bv.y;
    o.z = (v.z - mu) * inv * gv.z + bv.z;
    o.w = (v.w - mu) * inv * gv.w + bv.w;
    const size_t off = (size_t)row * EMB + t * 4;
    if (BF == 0) {
        *(float4*)(outf + off) = o;
    } else {
        *(uint2*)(ohi + off) = h4cvt(o);
    }
}

// ---------------- launch ----------------
extern "C" void kernel_launch(void* const* d_in, const int* in_sizes, int n_in,
                              void* d_out, int out_size)
{
    const float* value  = (const float*)d_in[0];
    const float* key_t  = (const float*)d_in[1];
    const float* query  = (const float*)d_in[2];
    const float* embed0 = (const float*)d_in[3];
    const float* Wq = (const float*)d_in[4];
    const float* bq = (const float*)d_in[5];
    const float* Wk = (const float*)d_in[6];
    const float* bk = (const float*)d_in[7];
    const float* Wv = (const float*)d_in[8];
    const float* bv = (const float*)d_in[9];
    const float* W1 = (const float*)d_in[10];
    const float* b1 = (const float*)d_in[11];
    const float* W2 = (const float*)d_in[12];
    const float* b2 = (const float*)d_in[13];
    const float* g1  = (const float*)d_in[14];
    const float* be1 = (const float*)d_in[15];
    const float* g2  = (const float*)d_in[16];
    const float* be2 = (const float*)d_in[17];

    h16 *p_qinh, *p_kinh, *p_vinh;
    h16 *p_wqh, *p_wkh, *p_wvh, *p_w1h, *p_w2h;
    h16 *p_qh, *p_kh, *p_vth, *p_ath, *p_xh, *p_hh;
    float *p_attnf, *p_x, *p_y;
    cudaGetSymbolAddress((void**)&p_qinh, qin_h);
    cudaGetSymbolAddress((void**)&p_kinh, kin_h);
    cudaGetSymbolAddress((void**)&p_vinh, vin_h);
    cudaGetSymbolAddress((void**)&p_wqh, wq_h);
    cudaGetSymbolAddress((void**)&p_wkh, wk_h);
    cudaGetSymbolAddress((void**)&p_wvh, wv_h);
    cudaGetSymbolAddress((void**)&p_w1h, w1_h);
    cudaGetSymbolAddress((void**)&p_w2h, w2_h);
    cudaGetSymbolAddress((void**)&p_qh, q_h);
    cudaGetSymbolAddress((void**)&p_kh, k_h);
    cudaGetSymbolAddress((void**)&p_vth, vt_h);
    cudaGetSymbolAddress((void**)&p_ath, at_h);
    cudaGetSymbolAddress((void**)&p_xh, x_h);
    cudaGetSymbolAddress((void**)&p_hh, h_h);
    cudaGetSymbolAddress((void**)&p_attnf, g_attnf);
    cudaGetSymbolAddress((void**)&p_x, g_x);
    cudaGetSymbolAddress((void**)&p_y, g_y);

    #define SET_SMEM(KER) cudaFuncSetAttribute(KER, cudaFuncAttributeMaxDynamicSharedMemorySize, SMEM_TOTAL)
    SET_SMEM((hmma_gemm<0,false,true,false>));   // q/k/FFN1-style fp16 out
    SET_SMEM((hmma_gemm<0,false,true,true>));    // vt (trans fp16 out)
    SET_SMEM((hmma_gemm<2,true,true,false>));    // attn (fp32 + fp16)
    SET_SMEM((hmma_gemm<0,true,false,false>));   // fp32 out (attn@V / FFN2)
    SET_SMEM((hmma_gemm<1,false,true,false>));   // FFN1 relu fp16 out

    float* outp = (float*)d_out;
    const long long outElems  = (long long)MROWS * EMB;
    const long long attnElems = (long long)NBATCH * SEQ * SEQ;
    float* attnf = ((long long)out_size >= outElems + attnElems) ? (outp + outElems) : p_attnf;

    dim3 blk(NTHR);
    dim3 blkc(256);
    const float scale = 1.0f / 32.0f;
    const size_t sQK = (size_t)SEQ * EMB;
    const size_t sAT = (size_t)SEQ * SEQ;
    const size_t sVT = (size_t)EMB * SEQ;

    // 0) input/weight conversions (hi planes only)
    cvt_h<<<MROWS*EMB/1024, blkc>>>(query, embed0, p_qinh);
    cvt_h<<<MROWS*EMB/1024, blkc>>>(key_t, embed0, p_kinh);
    cvt_h<<<MROWS*EMB/1024, blkc>>>(value, embed0, p_vinh);
    cvt_h<<<EMB*EMB/1024,   blkc>>>(Wq, nullptr, p_wqh);
    cvt_h<<<EMB*EMB/1024,   blkc>>>(Wk, nullptr, p_wkh);
    cvt_h<<<EMB*EMB/1024,   blkc>>>(Wv, nullptr, p_wvh);
    cvt_h<<<FFDIM*EMB/1024, blkc>>>(W1, nullptr, p_w1h);
    cvt_h<<<EMB*FFDIM/1024, blkc>>>(W2, nullptr, p_w2h);

    // 1) QKV projections (all hi-only)
    dim3 gQKV(EMB / 128, MROWS / 256, 1);
    hmma_gemm<0,false,true,false><<<gQKV, blk, SMEM_TOTAL>>>(
        p_qinh, p_wqh, bq, nullptr, p_qh, EMB, EMB, 0, 0, 0, 0.f);
    hmma_gemm<0,false,true,false><<<gQKV, blk, SMEM_TOTAL>>>(
        p_kinh, p_wkh, bk, nullptr, p_kh, EMB, EMB, 0, 0, 0, 0.f);
    hmma_gemm<0,false,true,true><<<gQKV, blk, SMEM_TOTAL>>>(
        p_vinh, p_wvh, bv, nullptr, p_vth, EMB, SEQ, 0, 0, 0, 0.f);

    // 2) attn = sigmoid(q @ k^T * scale): fp32 output + fp16 plane
    dim3 gS(SEQ / 128, SEQ / 256, NBATCH);
    hmma_gemm<2,true,true,false><<<gS, blk, SMEM_TOTAL>>>(
        p_qh, p_kh, nullptr, attnf, p_ath, EMB, SEQ, sQK, sQK, sAT, scale);

    // 3) x = attn @ v
    dim3 gAV(EMB / 128, SEQ / 256, NBATCH);
    hmma_gemm<0,true,false,false><<<gAV, blk, SMEM_TOTAL>>>(
        p_ath, p_vth, nullptr, p_x, nullptr, SEQ, EMB, sAT, sVT, sQK, 0.f);

    // 4) LN1 -> fp16
    layernorm_kernel<1><<<MROWS, 256>>>(p_x, g1, be1, nullptr, p_xh);

    // 5) FFN1 = relu(x @ W1^T + b1) -> fp16
    dim3 gF1(FFDIM / 128, MROWS / 256, 1);
    hmma_gemm<1,false,true,false><<<gF1, blk, SMEM_TOTAL>>>(
        p_xh, p_w1h, b1, nullptr, p_hh, EMB, FFDIM, 0, 0, 0, 0.f);

    // 6) FFN2 = h @ W2^T + b2 -> fp32
    dim3 gF2(EMB / 128, MROWS / 256, 1);
    hmma_gemm<0,true,false,false><<<gF2, blk, SMEM_TOTAL>>>(
        p_hh, p_w2h, b2, p_y, nullptr, FFDIM, EMB, 0, 0, 0, 0.f);

    // 7) LN2 -> out
    layernorm_kernel<0><<<MROWS, 256>>>(p_y, g2, be2, outp, nullptr);
}

// round 16
// speedup vs baseline: 2.7298x; 1.0522x over previous
#include <cuda_runtime.h>
#include <cuda_fp16.h>
#include <cstdint>
#include <math.h>

#define NBATCH 2
#define SEQ    4096
#define EMB    1024
#define FFDIM  4096
#define MROWS  (NBATCH*SEQ)   // 8192

typedef __half h16;

// ---------------- scratch (device globals; allocation-free) ----------------
__device__ h16 qin_h[MROWS*EMB];
__device__ h16 kin_h[MROWS*EMB];
__device__ h16 vin_h[MROWS*EMB];
__device__ h16 wq_h[EMB*EMB];
__device__ h16 wk_h[EMB*EMB];
__device__ h16 wv_h[EMB*EMB];
__device__ h16 w1_h[FFDIM*EMB];
__device__ h16 w2_h[EMB*FFDIM];
__device__ h16 q_h[MROWS*EMB];
__device__ h16 k_h[MROWS*EMB];
__device__ h16 vt_h[NBATCH*EMB*SEQ];
__device__ h16 at_h[(size_t)NBATCH*SEQ*SEQ];
__device__ h16 x_h[MROWS*EMB];
__device__ h16 h_h[MROWS*FFDIM];
__device__ float g_attnf[(size_t)NBATCH*SEQ*SEQ];
__device__ float g_x[MROWS*EMB];
__device__ float g_y[MROWS*EMB];

// ---------------- helpers ----------------
__device__ __forceinline__ uint32_t smem_u32(const void* p) {
    uint32_t a;
    asm("{ .reg .u64 t; cvta.to.shared.u64 t, %1; cvt.u32.u64 %0, t; }" : "=r"(a) : "l"(p));
    return a;
}
__device__ __forceinline__ void ldsm4(uint32_t r[4], uint32_t addr) {
    asm volatile("ldmatrix.sync.aligned.m8n8.x4.shared.b16 {%0,%1,%2,%3}, [%4];"
                 : "=r"(r[0]), "=r"(r[1]), "=r"(r[2]), "=r"(r[3]) : "r"(addr));
}
__device__ __forceinline__ void mma_f32(float c[4], const uint32_t a[4],
                                        uint32_t b0, uint32_t b1) {
    asm volatile("mma.sync.aligned.m16n8k16.row.col.f32.f16.f16.f32 "
                 "{%0,%1,%2,%3}, {%4,%5,%6,%7}, {%8,%9}, {%0,%1,%2,%3};"
                 : "+f"(c[0]), "+f"(c[1]), "+f"(c[2]), "+f"(c[3])
                 : "r"(a[0]), "r"(a[1]), "r"(a[2]), "r"(a[3]), "r"(b0), "r"(b1));
}
__device__ __forceinline__ void cpasync16(uint32_t dst, const void* src) {
    asm volatile("cp.async.cg.shared.global [%0], [%1], 16;" :: "r"(dst), "l"(src) : "memory");
}
#define CP_COMMIT() asm volatile("cp.async.commit_group;" ::: "memory")
#define CP_WAIT(n)  asm volatile("cp.async.wait_group %0;" :: "n"(n) : "memory")

// fp32x4 -> fp16x4 (uint2)
__device__ __forceinline__ uint2 h4cvt(const float4& f) {
    __half2 h01 = __floats2half2_rn(f.x, f.y);
    __half2 h23 = __floats2half2_rn(f.z, f.w);
    uint2 H;
    H.x = *reinterpret_cast<uint32_t*>(&h01);
    H.y = *reinterpret_cast<uint32_t*>(&h23);
    return H;
}

// ---------------- elementwise converter: hi = fp16(a [+ b]) ----------------
__global__ void __launch_bounds__(256)
cvt_h(const float* __restrict__ a, const float* __restrict__ b, h16* __restrict__ hi)
{
    const size_t i4 = ((size_t)blockIdx.x * 256 + threadIdx.x) * 4;
    float4 f = *(const float4*)(a + i4);
    if (b) {
        const float4 e = *(const float4*)(b + i4);
        f.x += e.x; f.y += e.y; f.z += e.z; f.w += e.w;
    }
    *(uint2*)(hi + i4) = h4cvt(f);
}

// ---------------- HMMA GEMM: C[M,N] = op( A[M,K] @ B[N,K]^T ) -----------------
// CTA tile 256x128, 512 threads, 16 warps 4x4, warp tile 64x32. K-chunk 128
// (two 64-K sub-planes per stage, identical SW128 addressing per sub-plane).
// Single product Ah*Bh with f32 accumulators.
// Stage 96KB: A(2x32K) | B(2x16K). NS=2 cp.async pipeline.
#define NS 2
#define A_SUB   32768
#define A_STAGE 65536
#define B_SUB   16384
#define STAGE_BYTES 98304
#define EPI_PITCH   132
#define EPI_PITCH_T 260
#define SMEM_TOTAL  (NS*STAGE_BYTES)    // 196608
#define NTHR 512

template<int OP, bool OUTF, bool OUTB, bool TRANS>
__global__ void __launch_bounds__(NTHR)
hmma_gemm(const h16* __restrict__ Ahi, const h16* __restrict__ Bhi,
          const float* __restrict__ bias,
          float* __restrict__ Cf, h16* __restrict__ Chi,
          int K, int ldC, size_t sA, size_t sB, size_t sC, float scale)
{
    extern __shared__ char smem[];
    const uint32_t sbase = smem_u32(smem);

    const int t = threadIdx.x;
    const int w = t >> 5, lane = t & 31;
    const int wm = w >> 2, wn = w & 3;            // warp grid 4 x 4

    const int bz = blockIdx.z;
    Ahi += (size_t)bz * sA;
    Bhi += (size_t)bz * sB;
    const int mBase = blockIdx.y * 256;
    const int nBase = blockIdx.x * 128;

    float accF[4][4][4];
    #pragma unroll
    for (int mi = 0; mi < 4; mi++)
        #pragma unroll
        for (int nj = 0; nj < 4; nj++)
            #pragma unroll
            for (int e = 0; e < 4; e++) accF[mi][nj][e] = 0.f;

    const int nk = K >> 7;    // 128-K chunks (K is 1024 or 4096)

    // cp.async mapping (per 64-K sub-plane; two sub-planes per chunk)
    const int arow = t >> 1;
    const uint32_t arx = ((uint32_t)(arow & 7)) << 4;
    const uint32_t arowoff = (uint32_t)arow * 128;
    const int brow = t >> 2;
    const uint32_t brx = ((uint32_t)(brow & 7)) << 4;
    const uint32_t browoff = (uint32_t)brow * 128;
    const size_t gArow = (size_t)(mBase + arow) * K;
    const size_t gBrow = (size_t)(nBase + brow) * K;

    auto ISSUE = [&](int kc, int s) {
        const int kb = kc << 7;
        const uint32_t st = sbase + (uint32_t)s * STAGE_BYTES;
        #pragma unroll
        for (int h = 0; h < 2; h++) {
            const int kh = kb + h * 64;
            #pragma unroll
            for (int c = 0; c < 4; c++) {
                const int col16 = (t & 1) * 4 + c;
                const uint32_t d = arowoff + (((uint32_t)col16 * 16) ^ arx);
                cpasync16(st + h * A_SUB + d, Ahi + gArow + kh + col16 * 8);
            }
            #pragma unroll
            for (int c = 0; c < 2; c++) {
                const int col16 = (t & 3) * 2 + c;
                const uint32_t d = browoff + (((uint32_t)col16 * 16) ^ brx);
                cpasync16(st + A_STAGE + h * B_SUB + d, Bhi + gBrow + kh + col16 * 8);
            }
        }
    };

    // ldmatrix addressing
    const uint32_t arow128 = (uint32_t)(wm * 64 + (lane & 15)) * 128;
    const uint32_t a16     = ((uint32_t)(lane >> 4)) << 4;
    const uint32_t axor    = ((uint32_t)(lane & 7)) << 4;
    const uint32_t brow128 = (uint32_t)(wn * 32 + ((lane >> 4) << 3) + (lane & 7)) * 128;
    const uint32_t b16     = ((uint32_t)((lane >> 3) & 1)) << 4;

    auto COMPUTE = [&](int s) {
        const uint32_t st = sbase + (uint32_t)s * STAGE_BYTES;
        #pragma unroll
        for (int h = 0; h < 2; h++) {
            const uint32_t stA = st + h * A_SUB;
            const uint32_t stB = st + A_STAGE + h * B_SUB;
            #pragma unroll
            for (int ki = 0; ki < 4; ki++) {
                const uint32_t kba = (uint32_t)(ki * 32);
                uint32_t Af[4][4], Bf[4][2];
                #pragma unroll
                for (int mi = 0; mi < 4; mi++)
                    ldsm4(Af[mi], stA + arow128 + mi * 2048 + ((kba + a16) ^ axor));
                #pragma unroll
                for (int nx = 0; nx < 2; nx++) {
                    uint32_t tb[4];
                    ldsm4(tb, stB + brow128 + nx * 2048 + ((kba + b16) ^ axor));
                    Bf[nx*2][0]   = tb[0]; Bf[nx*2][1]   = tb[1];
                    Bf[nx*2+1][0] = tb[2]; Bf[nx*2+1][1] = tb[3];
                }
                #pragma unroll
                for (int nj = 0; nj < 4; nj++)
                    #pragma unroll
                    for (int mi = 0; mi < 4; mi++)
                        mma_f32(accF[mi][nj], Af[mi], Bf[nj][0], Bf[nj][1]);
            }
        }
    };

    // NS=2 pipeline
    ISSUE(0, 0);
    CP_COMMIT();
    for (int kc = 0; kc < nk; kc++) {
        CP_WAIT(0);
        __syncthreads();
        if (kc + 1 < nk) { ISSUE(kc + 1, (kc + 1) & 1); CP_COMMIT(); }
        COMPUTE(kc & 1);
    }
    __syncthreads();

    // ---- epilogue
    float* epi = (float*)smem;
    const int g  = lane >> 2;
    const int tq = lane & 3;
    #pragma unroll
    for (int mi = 0; mi < 4; mi++) {
        #pragma unroll
        for (int nj = 0; nj < 4; nj++) {
            const int col = wn * 32 + nj * 8 + tq * 2;
            #pragma unroll
            for (int half = 0; half < 2; half++) {
                const int m = wm * 64 + mi * 16 + g + half * 8;
                float v0 = accF[mi][nj][half*2 + 0];
                float v1 = accF[mi][nj][half*2 + 1];
                if (OP == 2) {
                    v0 = 1.f / (1.f + __expf(-v0 * scale));
                    v1 = 1.f / (1.f + __expf(-v1 * scale));
                } else {
                    if (bias) { v0 += bias[nBase + col]; v1 += bias[nBase + col + 1]; }
                    if (OP == 1) { v0 = fmaxf(v0, 0.f); v1 = fmaxf(v1, 0.f); }
                }
                if (TRANS) {
                    epi[(col)     * EPI_PITCH_T + m] = v0;
                    epi[(col + 1) * EPI_PITCH_T + m] = v1;
                } else {
                    epi[m * EPI_PITCH + col]     = v0;
                    epi[m * EPI_PITCH + col + 1] = v1;
                }
            }
        }
    }
    __syncthreads();

    if (TRANS) {
        const int r  = t >> 2;            // 0..127
        const int ch = (t & 3) * 64;      // 0..192
        const size_t boffs = (size_t)(mBase >> 12) * ((size_t)EMB * SEQ);
        const size_t rowOff = boffs + (size_t)(nBase + r) * SEQ + (size_t)(mBase & (SEQ - 1)) + ch;
        #pragma unroll
        for (int i = 0; i < 16; i++) {
            const float* e = &epi[r * EPI_PITCH_T + ch + i * 4];
            const float4 f = make_float4(e[0], e[1], e[2], e[3]);
            if (OUTF) *(float4*)(Cf + rowOff + i * 4) = f;
            if (OUTB) *(uint2*)(Chi + rowOff + i * 4) = h4cvt(f);
        }
    } else {
        const int r  = t >> 1;            // 0..255
        const int ch = (t & 1) * 64;
        const size_t rowOff = (size_t)bz * sC + (size_t)(mBase + r) * ldC + nBase + ch;
        #pragma unroll
        for (int i = 0; i < 16; i++) {
            const float* e = &epi[r * EPI_PITCH + ch + i * 4];
            const float4 f = make_float4(e[0], e[1], e[2], e[3]);
            if (OUTF) *(float4*)(Cf + rowOff + i * 4) = f;
            if (OUTB) *(uint2*)(Chi + rowOff + i * 4) = h4cvt(f);
        }
    }
}

// ---------------- LayerNorm ----------------
// BF=0: write fp32; BF=1: write fp16 hi plane
template<int BF>
__global__ void __launch_bounds__(256)
layernorm_kernel(const float* __restrict__ x, const float* __restrict__ g,
                 const float* __restrict__ b, float* __restrict__ outf,
                 h16* __restrict__ ohi)
{
    const int row = blockIdx.x;
    const float* xr = x + (size_t)row * EMB;
    const int t = threadIdx.x;

    const float4 v = *(const float4*)(xr + t * 4);
    float s  = v.x + v.y + v.z + v.w;
    float ss = v.x * v.x + v.y * v.y + v.z * v.z + v.w * v.w;

    __shared__ float shs[8], shss[8], shmu[1], shinv[1];
    const int lane = t & 31, w = t >> 5;
    #pragma unroll
    for (int o = 16; o > 0; o >>= 1) {
        s  += __shfl_down_sync(0xffffffffu, s,  o);
        ss += __shfl_down_sync(0xffffffffu, ss, o);
    }
    if (lane == 0) { shs[w] = s; shss[w] = ss; }
    __syncthreads();
    if (w == 0) {
        float s2  = (lane < 8) ? shs[lane]  : 0.f;
        float ss2 = (lane < 8) ? shss[lane] : 0.f;
        #pragma unroll
        for (int o = 4; o > 0; o >>= 1) {
            s2  += __shfl_down_sync(0xffffffffu, s2,  o);
            ss2 += __shfl_down_sync(0xffffffffu, ss2, o);
        }
        if (lane == 0) {
            const float mu  = s2 * (1.f / EMB);
            const float var = ss2 * (1.f / EMB) - mu * mu;
            shmu[0]  = mu;
            shinv[0] = rsqrtf(var + 1e-5f);
        }
    }
    __syncthreads();
    const float mu = shmu[0], inv = shinv[0];

    const float4 gv = *(const float4*)(g + t * 4);
    const float4 bv = *(const float4*)(b + t * 4);
    float4 o;
    o.x = (v.x - mu) * inv * gv.x + bv.x;
    o.y = (v.y - mu) * inv * gv.y + bv.y;
    o.z = (v.z - mu) * inv * gv.z + bv.z;
    o.w = (v.w - mu) * inv * gv.w + bv.w;
    const size_t off = (size_t)row * EMB + t * 4;
    if (BF == 0) {
        *(float4*)(outf + off) = o;
    } else {
        *(uint2*)(ohi + off) = h4cvt(o);
    }
}

// ---------------- launch ----------------
extern "C" void kernel_launch(void* const* d_in, const int* in_sizes, int n_in,
                              void* d_out, int out_size)
{
    const float* value  = (const float*)d_in[0];
    const float* key_t  = (const float*)d_in[1];
    const float* query  = (const float*)d_in[2];
    const float* embed0 = (const float*)d_in[3];
    const float* Wq = (const float*)d_in[4];
    const float* bq = (const float*)d_in[5];
    const float* Wk = (const float*)d_in[6];
    const float* bk = (const float*)d_in[7];
    const float* Wv = (const float*)d_in[8];
    const float* bv = (const float*)d_in[9];
    const float* W1 = (const float*)d_in[10];
    const float* b1 = (const float*)d_in[11];
    const float* W2 = (const float*)d_in[12];
    const float* b2 = (const float*)d_in[13];
    const float* g1  = (const float*)d_in[14];
    const float* be1 = (const float*)d_in[15];
    const float* g2  = (const float*)d_in[16];
    const float* be2 = (const float*)d_in[17];

    h16 *p_qinh, *p_kinh, *p_vinh;
    h16 *p_wqh, *p_wkh, *p_wvh, *p_w1h, *p_w2h;
    h16 *p_qh, *p_kh, *p_vth, *p_ath, *p_xh, *p_hh;
    float *p_attnf, *p_x, *p_y;
    cudaGetSymbolAddress((void**)&p_qinh, qin_h);
    cudaGetSymbolAddress((void**)&p_kinh, kin_h);
    cudaGetSymbolAddress((void**)&p_vinh, vin_h);
    cudaGetSymbolAddress((void**)&p_wqh, wq_h);
    cudaGetSymbolAddress((void**)&p_wkh, wk_h);
    cudaGetSymbolAddress((void**)&p_wvh, wv_h);
    cudaGetSymbolAddress((void**)&p_w1h, w1_h);
    cudaGetSymbolAddress((void**)&p_w2h, w2_h);
    cudaGetSymbolAddress((void**)&p_qh, q_h);
    cudaGetSymbolAddress((void**)&p_kh, k_h);
    cudaGetSymbolAddress((void**)&p_vth, vt_h);
    cudaGetSymbolAddress((void**)&p_ath, at_h);
    cudaGetSymbolAddress((void**)&p_xh, x_h);
    cudaGetSymbolAddress((void**)&p_hh, h_h);
    cudaGetSymbolAddress((void**)&p_attnf, g_attnf);
    cudaGetSymbolAddress((void**)&p_x, g_x);
    cudaGetSymbolAddress((void**)&p_y, g_y);

    #define SET_SMEM(KER) cudaFuncSetAttribute(KER, cudaFuncAttributeMaxDynamicSharedMemorySize, SMEM_TOTAL)
    SET_SMEM((hmma_gemm<0,false,true,false>));   // q/k fp16 out
    SET_SMEM((hmma_gemm<0,false,true,true>));    // vt (trans fp16 out)
    SET_SMEM((hmma_gemm<2,true,true,false>));    // attn (fp32 + fp16)
    SET_SMEM((hmma_gemm<0,true,false,false>));   // fp32 out (attn@V / FFN2)
    SET_SMEM((hmma_gemm<1,false,true,false>));   // FFN1 relu fp16 out

    float* outp = (float*)d_out;
    const long long outElems  = (long long)MROWS * EMB;
    const long long attnElems = (long long)NBATCH * SEQ * SEQ;
    float* attnf = ((long long)out_size >= outElems + attnElems) ? (outp + outElems) : p_attnf;

    dim3 blk(NTHR);
    dim3 blkc(256);
    const float scale = 1.0f / 32.0f;
    const size_t sQK = (size_t)SEQ * EMB;
    const size_t sAT = (size_t)SEQ * SEQ;
    const size_t sVT = (size_t)EMB * SEQ;

    // 0) input/weight conversions (hi planes only)
    cvt_h<<<MROWS*EMB/1024, blkc>>>(query, embed0, p_qinh);
    cvt_h<<<MROWS*EMB/1024, blkc>>>(key_t, embed0, p_kinh);
    cvt_h<<<MROWS*EMB/1024, blkc>>>(value, embed0, p_vinh);
    cvt_h<<<EMB*EMB/1024,   blkc>>>(Wq, nullptr, p_wqh);
    cvt_h<<<EMB*EMB/1024,   blkc>>>(Wk, nullptr, p_wkh);
    cvt_h<<<EMB*EMB/1024,   blkc>>>(Wv, nullptr, p_wvh);
    cvt_h<<<FFDIM*EMB/1024, blkc>>>(W1, nullptr, p_w1h);
    cvt_h<<<EMB*FFDIM/1024, blkc>>>(W2, nullptr, p_w2h);

    // 1) QKV projections
    dim3 gQKV(EMB / 128, MROWS / 256, 1);
    hmma_gemm<0,false,true,false><<<gQKV, blk, SMEM_TOTAL>>>(
        p_qinh, p_wqh, bq, nullptr, p_qh, EMB, EMB, 0, 0, 0, 0.f);
    hmma_gemm<0,false,true,false><<<gQKV, blk, SMEM_TOTAL>>>(
        p_kinh, p_wkh, bk, nullptr, p_kh, EMB, EMB, 0, 0, 0, 0.f);
    hmma_gemm<0,false,true,true><<<gQKV, blk, SMEM_TOTAL>>>(
        p_vinh, p_wvh, bv, nullptr, p_vth, EMB, SEQ, 0, 0, 0, 0.f);

    // 2) attn = sigmoid(q @ k^T * scale): fp32 output + fp16 plane
    dim3 gS(SEQ / 128, SEQ / 256, NBATCH);
    hmma_gemm<2,true,true,false><<<gS, blk, SMEM_TOTAL>>>(
        p_qh, p_kh, nullptr, attnf, p_ath, EMB, SEQ, sQK, sQK, sAT, scale);

    // 3) x = attn @ v
    dim3 gAV(EMB / 128, SEQ / 256, NBATCH);
    hmma_gemm<0,true,false,false><<<gAV, blk, SMEM_TOTAL>>>(
        p_ath, p_vth, nullptr, p_x, nullptr, SEQ, EMB, sAT, sVT, sQK, 0.f);

    // 4) LN1 -> fp16
    layernorm_kernel<1><<<MROWS, 256>>>(p_x, g1, be1, nullptr, p_xh);

    // 5) FFN1 = relu(x @ W1^T + b1) -> fp16
    dim3 gF1(FFDIM / 128, MROWS / 256, 1);
    hmma_gemm<1,false,true,false><<<gF1, blk, SMEM_TOTAL>>>(
        p_xh, p_w1h, b1, nullptr, p_hh, EMB, FFDIM, 0, 0, 0, 0.f);

    // 6) FFN2 = h @ W2^T + b2 -> fp32
    dim3 gF2(EMB / 128, MROWS / 256, 1);
    hmma_gemm<0,true,false,false><<<gF2, blk, SMEM_TOTAL>>>(
        p_hh, p_w2h, b2, p_y, nullptr, FFDIM, EMB, 0, 0, 0, 0.f);

    // 7) LN2 -> out
    layernorm_kernel<0><<<MROWS, 256>>>(p_y, g2, be2, outp, nullptr);
}